// round 8
// baseline (speedup 1.0000x reference)
#include <cuda_runtime.h>
#include <cstdint>

// Problem constants
#define BATCH   4
#define SEQ     2048
#define CDIM    1024
#define NHEAD   16
#define DHEAD   64
#define MROWS   (BATCH * SEQ)          // 8192
#define BH      (BATCH * NHEAD)        // 64

// Scratch (device globals; no allocations allowed)
__device__ float g_q[(size_t)BH * SEQ * DHEAD];   // [BH][T][D]
__device__ float g_k[(size_t)BH * SEQ * DHEAD];
__device__ float g_v[(size_t)BH * SEQ * DHEAD];
__device__ float g_y[(size_t)MROWS * CDIM];       // [B,T,C], tf32-rounded
__device__ float g_xr[(size_t)MROWS * CDIM];      // x, tf32-rounded
__device__ float g_wt1[(size_t)3072 * 1024];      // w_attn^T, tf32-rounded
__device__ float g_wt2[(size_t)1024 * 1024];      // w_proj^T, tf32-rounded

// ---------------------------------------------------------------------------
// Helpers
// ---------------------------------------------------------------------------
__device__ __forceinline__ uint32_t smem_u32(const void* p) {
    uint32_t a;
    asm("{ .reg .u64 t; cvta.to.shared.u64 t, %1; cvt.u32.u64 %0, t; }" : "=r"(a) : "l"(p));
    return a;
}
__device__ __forceinline__ float to_tf32(float x) {
    float r;
    asm("cvt.rna.tf32.f32 %0, %1;" : "=f"(r) : "f"(x));
    return r;
}
__device__ __forceinline__ void cp16(uint32_t smem_dst, const void* gsrc) {
    asm volatile("cp.async.cg.shared.global [%0], [%1], 16;" :: "r"(smem_dst), "l"(gsrc));
}
#define CP_COMMIT() asm volatile("cp.async.commit_group;" ::: "memory")
#define CP_WAIT(N)  asm volatile("cp.async.wait_group %0;" :: "n"(N) : "memory")

// m16n8k8 tf32 MMA (row.col), fp32 accumulate
__device__ __forceinline__ void mma_tf32(float c[4], const float a[4], const float b[2]) {
    asm volatile(
        "mma.sync.aligned.m16n8k8.row.col.f32.tf32.tf32.f32 "
        "{%0,%1,%2,%3}, {%4,%5,%6,%7}, {%8,%9}, {%0,%1,%2,%3};\n"
        : "+f"(c[0]), "+f"(c[1]), "+f"(c[2]), "+f"(c[3])
        : "r"(__float_as_uint(a[0])), "r"(__float_as_uint(a[1])),
          "r"(__float_as_uint(a[2])), "r"(__float_as_uint(a[3])),
          "r"(__float_as_uint(b[0])), "r"(__float_as_uint(b[1])));
}

// ---------------------------------------------------------------------------
// Pre-pass kernels: tf32 rounding (+transpose for weights)
// ---------------------------------------------------------------------------
__global__ __launch_bounds__(256)
void round_copy(const float* __restrict__ src, float* __restrict__ dst)
{
    int i = blockIdx.x * blockDim.x + threadIdx.x;
    float4 v = ((const float4*)src)[i];
    v.x = to_tf32(v.x); v.y = to_tf32(v.y);
    v.z = to_tf32(v.z); v.w = to_tf32(v.w);
    ((float4*)dst)[i] = v;
}

__global__ __launch_bounds__(256)
void transpose_round(const float* __restrict__ W, float* __restrict__ WT, int N)
{
    __shared__ float tile[32][33];
    int n0 = blockIdx.x * 32;
    int k0 = blockIdx.y * 32;
    int tx = threadIdx.x, ty = threadIdx.y;     // 32 x 8
#pragma unroll
    for (int i = ty; i < 32; i += 8)
        tile[i][tx] = W[(size_t)(k0 + i) * N + n0 + tx];
    __syncthreads();
#pragma unroll
    for (int i = ty; i < 32; i += 8)
        WT[(size_t)(n0 + i) * 1024 + k0 + tx] = to_tf32(tile[tx][i]);
}

// ---------------------------------------------------------------------------
// tf32 mma.sync GEMM (exact R5 config — best measured)
// ---------------------------------------------------------------------------
#define PITCH_G 20
#define STG_FLOATS (128 * PITCH_G)                // 2560 floats per matrix
#define GEMM_SMEM  (3 * 2 * STG_FLOATS * 4)       // 61,440 B

template <bool SCATTER>
__global__ __launch_bounds__(128)
void gemm_mma(const float* __restrict__ A, const float* __restrict__ BT,
              const float* __restrict__ bias, float* __restrict__ out)
{
    extern __shared__ float smg[];

    const int tid = threadIdx.x;
    const int wid = tid >> 5;
    const int lane = tid & 31;
    const int wr = wid >> 1;
    const int wc = wid & 1;
    const int c0 = blockIdx.x * 128;
    const int r0 = blockIdx.y * 128;

    const float* Ab = A + (size_t)r0 * 1024;
    const float* Bb = BT + (size_t)c0 * 1024;

    float acc[4][8][4];
#pragma unroll
    for (int mt = 0; mt < 4; mt++)
#pragma unroll
        for (int nt = 0; nt < 8; nt++)
#pragma unroll
            for (int u = 0; u < 4; u++) acc[mt][nt][u] = 0.f;

    auto stage = [&](int c, int st) {
        float* sA = smg + st * 2 * STG_FLOATS;
        float* sB = sA + STG_FLOATS;
        const int k0 = c * 16;
#pragma unroll
        for (int i = 0; i < 4; i++) {
            int slot = tid + i * 128;
            int row = slot >> 2;
            int kq = (slot & 3) * 4;
            cp16(smem_u32(&sA[row * PITCH_G + kq]),
                 Ab + (size_t)row * 1024 + k0 + kq);
            cp16(smem_u32(&sB[row * PITCH_G + kq]),
                 Bb + (size_t)row * 1024 + k0 + kq);
        }
        CP_COMMIT();
    };

    stage(0, 0);
    stage(1, 1);

    const int lr = lane >> 2;
    const int lk = lane & 3;

    for (int c = 0; c < 64; c++) {
        const int st = c % 3;
        CP_WAIT(1);
        __syncthreads();
        if (c + 2 < 64) stage(c + 2, (c + 2) % 3);
        else CP_COMMIT();

        const float* tA = smg + st * 2 * STG_FLOATS + wr * 64 * PITCH_G;
        const float* tB = smg + st * 2 * STG_FLOATS + STG_FLOATS + wc * 64 * PITCH_G;
#pragma unroll
        for (int ks = 0; ks < 2; ks++) {
            float b[8][2];
#pragma unroll
            for (int nt = 0; nt < 8; nt++) {
                const float* Bn = &tB[(nt * 8 + lr) * PITCH_G + ks * 8];
                b[nt][0] = Bn[lk];
                b[nt][1] = Bn[4 + lk];
            }
#pragma unroll
            for (int mt = 0; mt < 4; mt++) {
                const float* Am = &tA[(mt * 16 + lr) * PITCH_G + ks * 8];
                float a[4];
                a[0] = Am[lk];
                a[1] = Am[8 * PITCH_G + lk];
                a[2] = Am[4 + lk];
                a[3] = Am[8 * PITCH_G + 4 + lk];
#pragma unroll
                for (int nt = 0; nt < 8; nt++)
                    mma_tf32(acc[mt][nt], a, b[nt]);
            }
        }
    }

    const int lc = (lane & 3) * 2;
#pragma unroll
    for (int mt = 0; mt < 4; mt++) {
#pragma unroll
        for (int nt = 0; nt < 8; nt++) {
            int m = r0 + wr * 64 + mt * 16 + lr;
            int n = c0 + wc * 64 + nt * 8 + lc;
            float b0 = bias[n], b1 = bias[n + 1];
            float2 v0 = make_float2(acc[mt][nt][0] + b0, acc[mt][nt][1] + b1);
            float2 v1 = make_float2(acc[mt][nt][2] + b0, acc[mt][nt][3] + b1);
            if (SCATTER) {
                int which = n >> 10;
                int cc = n & 1023;
                int h = cc >> 6;
                int d = cc & 63;
                int bb = m >> 11;
                int t = m & 2047;
                float* dst = (which == 0) ? g_q : (which == 1) ? g_k : g_v;
                size_t base = (size_t)(bb * NHEAD + h) * SEQ;
                *(float2*)(dst + (base + t) * DHEAD + d) = v0;
                *(float2*)(dst + (base + t + 8) * DHEAD + d) = v1;
            } else {
                *(float2*)(out + (size_t)m * 1024 + n) = v0;
                *(float2*)(out + (size_t)(m + 8) * 1024 + n) = v1;
            }
        }
    }
}

// ---------------------------------------------------------------------------
// Tensor-core flash attention, 128-wide softmax batching, 4 K/V buffers.
// Two __syncthreads per 128 cols (half of R5's rate); softmax state update,
// shuffles, and O-rescale amortized over 128 cols.
// ---------------------------------------------------------------------------
#define AP 68
#define SMEM_ATTN ((4 * 64 + 4 * 64 + 128) * AP * 4)   // 174,080 B

__global__ __launch_bounds__(256)
void attn_mma()
{
    extern __shared__ float sm[];
    float* sK[4] = {sm,               sm + 64 * AP,
                    sm + 2 * 64 * AP, sm + 3 * 64 * AP};
    float* sV[4] = {sm + 4 * 64 * AP, sm + 5 * 64 * AP,
                    sm + 6 * 64 * AP, sm + 7 * 64 * AP};
    float* sP = sm + 8 * 64 * AP;

    const int qi = (int)gridDim.x - 1 - (int)blockIdx.x;
    const int bh = blockIdx.y;
    const int tid = threadIdx.x;
    const int wid = tid >> 5;
    const int lane = tid & 31;
    const int lr = lane >> 2;
    const int lk = lane & 3;
    const int warp_m = wid * 16;
    const int q0 = qi * 128;

    const float* Kg = g_k + (size_t)bh * SEQ * DHEAD;
    const float* Vg = g_v + (size_t)bh * SEQ * DHEAD;

    auto stage = [&](int kt, int b) {
        const int k0 = kt * 64;
#pragma unroll
        for (int i = 0; i < 4; i++) {
            int slot = tid + i * 256;
            int row = slot >> 4;
            int c4 = (slot & 15) * 4;
            cp16(smem_u32(&sK[b][row * AP + c4]), Kg + (size_t)(k0 + row) * 64 + c4);
            cp16(smem_u32(&sV[b][row * AP + c4]), Vg + (size_t)(k0 + row) * 64 + c4);
        }
        CP_COMMIT();
    };

    const float scale = 0.125f;
    float qf[8][4];
    {
        const float* Qw = g_q + ((size_t)bh * SEQ + q0 + warp_m) * DHEAD;
#pragma unroll
        for (int ks = 0; ks < 8; ks++) {
            qf[ks][0] = to_tf32(Qw[lr * 64 + ks * 8 + lk] * scale);
            qf[ks][1] = to_tf32(Qw[(lr + 8) * 64 + ks * 8 + lk] * scale);
            qf[ks][2] = to_tf32(Qw[lr * 64 + ks * 8 + 4 + lk] * scale);
            qf[ks][3] = to_tf32(Qw[(lr + 8) * 64 + ks * 8 + 4 + lk] * scale);
        }
    }

    float o[8][4];
#pragma unroll
    for (int nt = 0; nt < 8; nt++)
#pragma unroll
        for (int u = 0; u < 4; u++) o[nt][u] = 0.f;

    float m0 = -1e30f, m1 = -1e30f, l0 = 0.f, l1 = 0.f;
    const int row0 = q0 + warp_m + lr;
    const int row1 = row0 + 8;
    const int lim = q0 + warp_m + 15;

    float* Pr0 = &sP[(warp_m + lr) * AP];
    float* Pr1 = &sP[(warp_m + lr + 8) * AP];

    const int npairs = qi + 1;
    stage(0, 0);
    stage(1, 1);

    for (int p = 0; p < npairs; p++) {
        const int bA = (2 * p) & 3;
        const int bB = (2 * p + 1) & 3;
        const int k0a = p * 128;
        const int k0b = k0a + 64;

        __syncthreads();             // pair p-1 fully consumed (its bufs free)
        if (p + 1 < npairs) {
            stage(2 * p + 2, bA ^ 2);   // pair p+1 into the other buffer pair
            stage(2 * p + 3, bB ^ 2);
        } else {
            CP_COMMIT(); CP_COMMIT();
        }
        CP_WAIT(2);                  // pair p resident (pair p+1 pending)
        __syncthreads();             // cross-thread visibility of pair p

        if (k0a > lim) continue;
        const bool skipB = (k0b > lim);
        const float* cKA = sK[bA];
        const float* cKB = sK[bB];
        const float* cVA = sV[bA];
        const float* cVB = sV[bB];

        float s[16][4];
#pragma unroll
        for (int nt = 0; nt < 16; nt++) {
            float init = (nt >= 8 && skipB) ? -1e30f : 0.f;
#pragma unroll
            for (int u = 0; u < 4; u++) s[nt][u] = init;
        }

#pragma unroll
        for (int nt = 0; nt < 8; nt++) {
            const float* Kn = &cKA[(nt * 8 + lr) * AP];
#pragma unroll
            for (int ks = 0; ks < 8; ks++) {
                float b[2] = {Kn[ks * 8 + lk], Kn[ks * 8 + 4 + lk]};
                mma_tf32(s[nt], qf[ks], b);
            }
        }
        if (!skipB) {
#pragma unroll
            for (int nt = 0; nt < 8; nt++) {
                const float* Kn = &cKB[(nt * 8 + lr) * AP];
#pragma unroll
                for (int ks = 0; ks < 8; ks++) {
                    float b[2] = {Kn[ks * 8 + lk], Kn[ks * 8 + 4 + lk]};
                    mma_tf32(s[8 + nt], qf[ks], b);
                }
            }
        }

        const bool need_mask = (k0a + 127 > row0);
        float rmax0 = -1e30f, rmax1 = -1e30f;
#pragma unroll
        for (int nt = 0; nt < 16; nt++) {
            if (need_mask) {
                const int cb = k0a + nt * 8 + 2 * lk;
                if (cb     > row0) s[nt][0] = -1e30f;
                if (cb + 1 > row0) s[nt][1] = -1e30f;
                if (cb     > row1) s[nt][2] = -1e30f;
                if (cb + 1 > row1) s[nt][3] = -1e30f;
            }
            rmax0 = fmaxf(rmax0, fmaxf(s[nt][0], s[nt][1]));
            rmax1 = fmaxf(rmax1, fmaxf(s[nt][2], s[nt][3]));
        }
        rmax0 = fmaxf(rmax0, __shfl_xor_sync(0xffffffffu, rmax0, 1));
        rmax0 = fmaxf(rmax0, __shfl_xor_sync(0xffffffffu, rmax0, 2));
        rmax1 = fmaxf(rmax1, __shfl_xor_sync(0xffffffffu, rmax1, 1));
        rmax1 = fmaxf(rmax1, __shfl_xor_sync(0xffffffffu, rmax1, 2));

        const float mn0 = fmaxf(m0, rmax0);
        const float mn1 = fmaxf(m1, rmax1);
        const float a0 = __expf(m0 - mn0);
        const float a1 = __expf(m1 - mn1);
        m0 = mn0; m1 = mn1;

        float rs0 = 0.f, rs1 = 0.f;
#pragma unroll
        for (int nt = 0; nt < 16; nt++) {
            s[nt][0] = __expf(s[nt][0] - mn0);
            s[nt][1] = __expf(s[nt][1] - mn0);
            s[nt][2] = __expf(s[nt][2] - mn1);
            s[nt][3] = __expf(s[nt][3] - mn1);
            rs0 += s[nt][0] + s[nt][1];
            rs1 += s[nt][2] + s[nt][3];
        }
        rs0 += __shfl_xor_sync(0xffffffffu, rs0, 1);
        rs0 += __shfl_xor_sync(0xffffffffu, rs0, 2);
        rs1 += __shfl_xor_sync(0xffffffffu, rs1, 1);
        rs1 += __shfl_xor_sync(0xffffffffu, rs1, 2);
        l0 = l0 * a0 + rs0;
        l1 = l1 * a1 + rs1;

#pragma unroll
        for (int nt = 0; nt < 8; nt++) {
            o[nt][0] *= a0; o[nt][1] *= a0;
            o[nt][2] *= a1; o[nt][3] *= a1;
        }

        // PV half A
#pragma unroll
        for (int nt = 0; nt < 8; nt++) {
            *(float2*)&Pr0[nt * 8 + 2 * lk] =
                make_float2(to_tf32(s[nt][0]), to_tf32(s[nt][1]));
            *(float2*)&Pr1[nt * 8 + 2 * lk] =
                make_float2(to_tf32(s[nt][2]), to_tf32(s[nt][3]));
        }
        __syncwarp();
#pragma unroll
        for (int ks = 0; ks < 8; ks++) {
            float ap[4];
            ap[0] = Pr0[ks * 8 + lk];
            ap[1] = Pr1[ks * 8 + lk];
            ap[2] = Pr0[ks * 8 + 4 + lk];
            ap[3] = Pr1[ks * 8 + 4 + lk];
#pragma unroll
            for (int nt = 0; nt < 8; nt++) {
                float b[2] = {cVA[(ks * 8 + lk) * AP + nt * 8 + lr],
                              cVA[(ks * 8 + 4 + lk) * AP + nt * 8 + lr]};
                mma_tf32(o[nt], ap, b);
            }
        }
        __syncwarp();

        if (!skipB) {
            // PV half B (reuse P strip)
#pragma unroll
            for (int nt = 0; nt < 8; nt++) {
                *(float2*)&Pr0[nt * 8 + 2 * lk] =
                    make_float2(to_tf32(s[8 + nt][0]), to_tf32(s[8 + nt][1]));
                *(float2*)&Pr1[nt * 8 + 2 * lk] =
                    make_float2(to_tf32(s[8 + nt][2]), to_tf32(s[8 + nt][3]));
            }
            __syncwarp();
#pragma unroll
            for (int ks = 0; ks < 8; ks++) {
                float ap[4];
                ap[0] = Pr0[ks * 8 + lk];
                ap[1] = Pr1[ks * 8 + lk];
                ap[2] = Pr0[ks * 8 + 4 + lk];
                ap[3] = Pr1[ks * 8 + 4 + lk];
#pragma unroll
                for (int nt = 0; nt < 8; nt++) {
                    float b[2] = {cVB[(ks * 8 + lk) * AP + nt * 8 + lr],
                                  cVB[(ks * 8 + 4 + lk) * AP + nt * 8 + lr]};
                    mma_tf32(o[nt], ap, b);
                }
            }
            __syncwarp();
        }
    }

    const float inv0 = 1.f / l0;
    const float inv1 = 1.f / l1;
    const int b = bh >> 4;
    const int h = bh & 15;
    float* y0 = g_y + ((size_t)(b * SEQ + row0)) * CDIM + h * 64;
    float* y1 = g_y + ((size_t)(b * SEQ + row1)) * CDIM + h * 64;
#pragma unroll
    for (int nt = 0; nt < 8; nt++) {
        int d = nt * 8 + 2 * lk;
        *(float2*)(y0 + d) = make_float2(to_tf32(o[nt][0] * inv0),
                                         to_tf32(o[nt][1] * inv0));
        *(float2*)(y1 + d) = make_float2(to_tf32(o[nt][2] * inv1),
                                         to_tf32(o[nt][3] * inv1));
    }
}

// ---------------------------------------------------------------------------
extern "C" void kernel_launch(void* const* d_in, const int* in_sizes, int n_in,
                              void* d_out, int out_size)
{
    const float* x      = (const float*)d_in[0];
    const float* w_attn = (const float*)d_in[1];
    const float* b_attn = (const float*)d_in[2];
    const float* w_proj = (const float*)d_in[3];
    const float* b_proj = (const float*)d_in[4];
    float* out = (float*)d_out;

    cudaFuncSetAttribute(attn_mma, cudaFuncAttributeMaxDynamicSharedMemorySize,
                         SMEM_ATTN);
    cudaFuncSetAttribute(gemm_mma<true>, cudaFuncAttributeMaxDynamicSharedMemorySize,
                         GEMM_SMEM);
    cudaFuncSetAttribute(gemm_mma<false>, cudaFuncAttributeMaxDynamicSharedMemorySize,
                         GEMM_SMEM);

    void* y_ptr = nullptr;   cudaGetSymbolAddress(&y_ptr, g_y);
    void* xr_ptr = nullptr;  cudaGetSymbolAddress(&xr_ptr, g_xr);
    void* wt1_ptr = nullptr; cudaGetSymbolAddress(&wt1_ptr, g_wt1);
    void* wt2_ptr = nullptr; cudaGetSymbolAddress(&wt2_ptr, g_wt2);

    round_copy<<<(MROWS * CDIM / 4) / 256, 256>>>(x, (float*)xr_ptr);
    transpose_round<<<dim3(3072 / 32, 1024 / 32), dim3(32, 8)>>>(w_attn, (float*)wt1_ptr, 3072);
    transpose_round<<<dim3(1024 / 32, 1024 / 32), dim3(32, 8)>>>(w_proj, (float*)wt2_ptr, 1024);

    gemm_mma<true><<<dim3(3072 / 128, MROWS / 128), 128, GEMM_SMEM>>>(
        (const float*)xr_ptr, (const float*)wt1_ptr, b_attn, nullptr);

    attn_mma<<<dim3(SEQ / 128, BH), 256, SMEM_ATTN>>>();

    gemm_mma<false><<<dim3(1024 / 128, MROWS / 128), 128, GEMM_SMEM>>>(
        (const float*)y_ptr, (const float*)wt2_ptr, b_proj, out);
}

// round 9
// speedup vs baseline: 1.5654x; 1.5654x over previous
#include <cuda_runtime.h>
#include <cstdint>

// Problem constants
#define BATCH   4
#define SEQ     2048
#define CDIM    1024
#define NHEAD   16
#define DHEAD   64
#define MROWS   (BATCH * SEQ)          // 8192
#define BH      (BATCH * NHEAD)        // 64

// Scratch (device globals; no allocations allowed)
__device__ float g_q[(size_t)BH * SEQ * DHEAD];   // [BH][T][D]
__device__ float g_k[(size_t)BH * SEQ * DHEAD];
__device__ float g_v[(size_t)BH * SEQ * DHEAD];
__device__ float g_y[(size_t)MROWS * CDIM];       // [B,T,C], tf32-rounded
__device__ float g_xr[(size_t)MROWS * CDIM];      // x, tf32-rounded
__device__ float g_wt1[(size_t)3072 * 1024];      // w_attn^T, tf32-rounded
__device__ float g_wt2[(size_t)1024 * 1024];      // w_proj^T, tf32-rounded

// ---------------------------------------------------------------------------
// Helpers
// ---------------------------------------------------------------------------
__device__ __forceinline__ uint32_t smem_u32(const void* p) {
    uint32_t a;
    asm("{ .reg .u64 t; cvta.to.shared.u64 t, %1; cvt.u32.u64 %0, t; }" : "=r"(a) : "l"(p));
    return a;
}
__device__ __forceinline__ float to_tf32(float x) {
    float r;
    asm("cvt.rna.tf32.f32 %0, %1;" : "=f"(r) : "f"(x));
    return r;
}
__device__ __forceinline__ void cp16(uint32_t smem_dst, const void* gsrc) {
    asm volatile("cp.async.cg.shared.global [%0], [%1], 16;" :: "r"(smem_dst), "l"(gsrc));
}
#define CP_COMMIT() asm volatile("cp.async.commit_group;" ::: "memory")
#define CP_WAIT(N)  asm volatile("cp.async.wait_group %0;" :: "n"(N) : "memory")

// m16n8k8 tf32 MMA (row.col), fp32 accumulate
__device__ __forceinline__ void mma_tf32(float c[4], const float a[4], const float b[2]) {
    asm volatile(
        "mma.sync.aligned.m16n8k8.row.col.f32.tf32.tf32.f32 "
        "{%0,%1,%2,%3}, {%4,%5,%6,%7}, {%8,%9}, {%0,%1,%2,%3};\n"
        : "+f"(c[0]), "+f"(c[1]), "+f"(c[2]), "+f"(c[3])
        : "r"(__float_as_uint(a[0])), "r"(__float_as_uint(a[1])),
          "r"(__float_as_uint(a[2])), "r"(__float_as_uint(a[3])),
          "r"(__float_as_uint(b[0])), "r"(__float_as_uint(b[1])));
}

// ---------------------------------------------------------------------------
// Pre-pass kernels: tf32 rounding (+transpose for weights)
// ---------------------------------------------------------------------------
__global__ __launch_bounds__(256)
void round_copy(const float* __restrict__ src, float* __restrict__ dst)
{
    int i = blockIdx.x * blockDim.x + threadIdx.x;
    float4 v = ((const float4*)src)[i];
    v.x = to_tf32(v.x); v.y = to_tf32(v.y);
    v.z = to_tf32(v.z); v.w = to_tf32(v.w);
    ((float4*)dst)[i] = v;
}

__global__ __launch_bounds__(256)
void transpose_round(const float* __restrict__ W, float* __restrict__ WT, int N)
{
    __shared__ float tile[32][33];
    int n0 = blockIdx.x * 32;
    int k0 = blockIdx.y * 32;
    int tx = threadIdx.x, ty = threadIdx.y;     // 32 x 8
#pragma unroll
    for (int i = ty; i < 32; i += 8)
        tile[i][tx] = W[(size_t)(k0 + i) * N + n0 + tx];
    __syncthreads();
#pragma unroll
    for (int i = ty; i < 32; i += 8)
        WT[(size_t)(n0 + i) * 1024 + k0 + tx] = to_tf32(tile[tx][i]);
}

// ---------------------------------------------------------------------------
// tf32 mma.sync GEMM (exact R5 config — best measured): 128x128 CTA tile,
// 4 warps of 64x64 output each, BK=16, 3-stage cp.async pipeline, one
// __syncthreads per slab.
// ---------------------------------------------------------------------------
#define PITCH_G 20
#define STG_FLOATS (128 * PITCH_G)                // 2560 floats per matrix
#define GEMM_SMEM  (3 * 2 * STG_FLOATS * 4)       // 61,440 B

template <bool SCATTER>
__global__ __launch_bounds__(128)
void gemm_mma(const float* __restrict__ A, const float* __restrict__ BT,
              const float* __restrict__ bias, float* __restrict__ out)
{
    extern __shared__ float smg[];

    const int tid = threadIdx.x;
    const int wid = tid >> 5;
    const int lane = tid & 31;
    const int wr = wid >> 1;
    const int wc = wid & 1;
    const int c0 = blockIdx.x * 128;
    const int r0 = blockIdx.y * 128;

    const float* Ab = A + (size_t)r0 * 1024;
    const float* Bb = BT + (size_t)c0 * 1024;

    float acc[4][8][4];
#pragma unroll
    for (int mt = 0; mt < 4; mt++)
#pragma unroll
        for (int nt = 0; nt < 8; nt++)
#pragma unroll
            for (int u = 0; u < 4; u++) acc[mt][nt][u] = 0.f;

    auto stage = [&](int c, int st) {
        float* sA = smg + st * 2 * STG_FLOATS;
        float* sB = sA + STG_FLOATS;
        const int k0 = c * 16;
#pragma unroll
        for (int i = 0; i < 4; i++) {
            int slot = tid + i * 128;
            int row = slot >> 2;
            int kq = (slot & 3) * 4;
            cp16(smem_u32(&sA[row * PITCH_G + kq]),
                 Ab + (size_t)row * 1024 + k0 + kq);
            cp16(smem_u32(&sB[row * PITCH_G + kq]),
                 Bb + (size_t)row * 1024 + k0 + kq);
        }
        CP_COMMIT();
    };

    stage(0, 0);
    stage(1, 1);

    const int lr = lane >> 2;
    const int lk = lane & 3;

    for (int c = 0; c < 64; c++) {
        const int st = c % 3;
        CP_WAIT(1);
        __syncthreads();
        if (c + 2 < 64) stage(c + 2, (c + 2) % 3);
        else CP_COMMIT();

        const float* tA = smg + st * 2 * STG_FLOATS + wr * 64 * PITCH_G;
        const float* tB = smg + st * 2 * STG_FLOATS + STG_FLOATS + wc * 64 * PITCH_G;
#pragma unroll
        for (int ks = 0; ks < 2; ks++) {
            float b[8][2];
#pragma unroll
            for (int nt = 0; nt < 8; nt++) {
                const float* Bn = &tB[(nt * 8 + lr) * PITCH_G + ks * 8];
                b[nt][0] = Bn[lk];
                b[nt][1] = Bn[4 + lk];
            }
#pragma unroll
            for (int mt = 0; mt < 4; mt++) {
                const float* Am = &tA[(mt * 16 + lr) * PITCH_G + ks * 8];
                float a[4];
                a[0] = Am[lk];
                a[1] = Am[8 * PITCH_G + lk];
                a[2] = Am[4 + lk];
                a[3] = Am[8 * PITCH_G + 4 + lk];
#pragma unroll
                for (int nt = 0; nt < 8; nt++)
                    mma_tf32(acc[mt][nt], a, b[nt]);
            }
        }
    }

    const int lc = (lane & 3) * 2;
#pragma unroll
    for (int mt = 0; mt < 4; mt++) {
#pragma unroll
        for (int nt = 0; nt < 8; nt++) {
            int m = r0 + wr * 64 + mt * 16 + lr;
            int n = c0 + wc * 64 + nt * 8 + lc;
            float b0 = bias[n], b1 = bias[n + 1];
            float2 v0 = make_float2(acc[mt][nt][0] + b0, acc[mt][nt][1] + b1);
            float2 v1 = make_float2(acc[mt][nt][2] + b0, acc[mt][nt][3] + b1);
            if (SCATTER) {
                int which = n >> 10;
                int cc = n & 1023;
                int h = cc >> 6;
                int d = cc & 63;
                int bb = m >> 11;
                int t = m & 2047;
                float* dst = (which == 0) ? g_q : (which == 1) ? g_k : g_v;
                size_t base = (size_t)(bb * NHEAD + h) * SEQ;
                *(float2*)(dst + (base + t) * DHEAD + d) = v0;
                *(float2*)(dst + (base + t + 8) * DHEAD + d) = v1;
            } else {
                *(float2*)(out + (size_t)m * 1024 + n) = v0;
                *(float2*)(out + (size_t)(m + 8) * 1024 + n) = v1;
            }
        }
    }
}

// ---------------------------------------------------------------------------
// Tensor-core flash attention (tf32 mma.sync) — R5 structure with:
//  * V pitch 72 (conflict-free PV fragment LDS: 8*lk+lr+8*nt is a bank perm)
//  * 3-buffer K/V pipeline, ONE __syncthreads per 64-col tile
// 64-col softmax granularity (register footprint identical to R5).
// ---------------------------------------------------------------------------
#define APK 68
#define APV 72
#define KBUF (64 * APK)
#define VBUF (64 * APV)
#define SMEM_ATTN ((3 * KBUF + 3 * VBUF + 128 * APK) * 4)   // 142,336 B

__global__ __launch_bounds__(256)
void attn_mma()
{
    extern __shared__ float sm[];
    float* sK[3] = {sm, sm + KBUF, sm + 2 * KBUF};
    float* sV[3] = {sm + 3 * KBUF, sm + 3 * KBUF + VBUF, sm + 3 * KBUF + 2 * VBUF};
    float* sP = sm + 3 * KBUF + 3 * VBUF;    // [128][APK] per-warp-private rows

    const int qi = (int)gridDim.x - 1 - (int)blockIdx.x;   // heavy tiles first
    const int bh = blockIdx.y;
    const int tid = threadIdx.x;
    const int wid = tid >> 5;
    const int lane = tid & 31;
    const int lr = lane >> 2;        // 0..7
    const int lk = lane & 3;         // 0..3
    const int warp_m = wid * 16;
    const int q0 = qi * 128;

    const float* Kg = g_k + (size_t)bh * SEQ * DHEAD;
    const float* Vg = g_v + (size_t)bh * SEQ * DHEAD;

    // stage K/V tile kt into buffer b (cp.async; 4+4 float4 per thread)
    auto stage = [&](int kt, int b) {
        const int k0 = kt * 64;
#pragma unroll
        for (int i = 0; i < 4; i++) {
            int slot = tid + i * 256;        // 0..1023
            int row = slot >> 4;             // 0..63
            int c4 = (slot & 15) * 4;        // 0..60
            cp16(smem_u32(&sK[b][row * APK + c4]), Kg + (size_t)(k0 + row) * 64 + c4);
            cp16(smem_u32(&sV[b][row * APV + c4]), Vg + (size_t)(k0 + row) * 64 + c4);
        }
        CP_COMMIT();
    };

    // Q fragments (scale folded in): A-frag per k-step (8 steps of k=8)
    const float scale = 0.125f;      // 1/sqrt(64)
    float qf[8][4];
    {
        const float* Qw = g_q + ((size_t)bh * SEQ + q0 + warp_m) * DHEAD;
#pragma unroll
        for (int ks = 0; ks < 8; ks++) {
            qf[ks][0] = to_tf32(Qw[lr * 64 + ks * 8 + lk] * scale);
            qf[ks][1] = to_tf32(Qw[(lr + 8) * 64 + ks * 8 + lk] * scale);
            qf[ks][2] = to_tf32(Qw[lr * 64 + ks * 8 + 4 + lk] * scale);
            qf[ks][3] = to_tf32(Qw[(lr + 8) * 64 + ks * 8 + 4 + lk] * scale);
        }
    }

    float o[8][4];
#pragma unroll
    for (int nt = 0; nt < 8; nt++)
#pragma unroll
        for (int u = 0; u < 4; u++) o[nt][u] = 0.f;

    float m0 = -1e30f, m1 = -1e30f, l0 = 0.f, l1 = 0.f;
    const int row0 = q0 + warp_m + lr;
    const int row1 = row0 + 8;

    float* Pr0 = &sP[(warp_m + lr) * APK];
    float* Pr1 = &sP[(warp_m + lr + 8) * APK];

    const int nkt = (qi + 1) * 2;
    stage(0, 0);
    if (nkt > 1) stage(1, 1); else CP_COMMIT();

    for (int kt = 0; kt < nkt; kt++) {
        const int st = kt % 3;
        const int k0 = kt * 64;

        CP_WAIT(1);                  // tile kt resident (kt+1 pending)
        __syncthreads();             // visibility; all warps finished kt-1
        if (kt + 2 < nkt) stage(kt + 2, (kt + 2) % 3);
        else CP_COMMIT();            // keep group accounting aligned

        // Warps fully above the diagonal of this K tile have nothing to do
        if (k0 > q0 + warp_m + 15) continue;

        const float* cK = sK[st];
        const float* cV = sV[st];

        // S = Q K^T   (16 x 64 per warp)
        float s[8][4];
#pragma unroll
        for (int nt = 0; nt < 8; nt++)
#pragma unroll
            for (int u = 0; u < 4; u++) s[nt][u] = 0.f;

#pragma unroll
        for (int nt = 0; nt < 8; nt++) {
            const float* Kn = &cK[(nt * 8 + lr) * APK];
#pragma unroll
            for (int ks = 0; ks < 8; ks++) {
                float b[2] = {Kn[ks * 8 + lk], Kn[ks * 8 + 4 + lk]};
                mma_tf32(s[nt], qf[ks], b);
            }
        }

        // Causal mask (scale pre-folded) + row max
        const bool need_mask = (k0 + 63 > row0);
        float rmax0 = -1e30f, rmax1 = -1e30f;
#pragma unroll
        for (int nt = 0; nt < 8; nt++) {
            if (need_mask) {
                const int cb = k0 + nt * 8 + 2 * lk;
                if (cb     > row0) s[nt][0] = -1e30f;
                if (cb + 1 > row0) s[nt][1] = -1e30f;
                if (cb     > row1) s[nt][2] = -1e30f;
                if (cb + 1 > row1) s[nt][3] = -1e30f;
            }
            rmax0 = fmaxf(rmax0, fmaxf(s[nt][0], s[nt][1]));
            rmax1 = fmaxf(rmax1, fmaxf(s[nt][2], s[nt][3]));
        }
        rmax0 = fmaxf(rmax0, __shfl_xor_sync(0xffffffffu, rmax0, 1));
        rmax0 = fmaxf(rmax0, __shfl_xor_sync(0xffffffffu, rmax0, 2));
        rmax1 = fmaxf(rmax1, __shfl_xor_sync(0xffffffffu, rmax1, 1));
        rmax1 = fmaxf(rmax1, __shfl_xor_sync(0xffffffffu, rmax1, 2));

        const float mn0 = fmaxf(m0, rmax0);
        const float mn1 = fmaxf(m1, rmax1);
        const float a0 = __expf(m0 - mn0);
        const float a1 = __expf(m1 - mn1);
        m0 = mn0; m1 = mn1;

        float rs0 = 0.f, rs1 = 0.f;
#pragma unroll
        for (int nt = 0; nt < 8; nt++) {
            s[nt][0] = __expf(s[nt][0] - mn0);
            s[nt][1] = __expf(s[nt][1] - mn0);
            s[nt][2] = __expf(s[nt][2] - mn1);
            s[nt][3] = __expf(s[nt][3] - mn1);
            rs0 += s[nt][0] + s[nt][1];
            rs1 += s[nt][2] + s[nt][3];
        }
        rs0 += __shfl_xor_sync(0xffffffffu, rs0, 1);
        rs0 += __shfl_xor_sync(0xffffffffu, rs0, 2);
        rs1 += __shfl_xor_sync(0xffffffffu, rs1, 1);
        rs1 += __shfl_xor_sync(0xffffffffu, rs1, 2);
        l0 = l0 * a0 + rs0;
        l1 = l1 * a1 + rs1;

#pragma unroll
        for (int nt = 0; nt < 8; nt++) {
            o[nt][0] *= a0; o[nt][1] *= a0;
            o[nt][2] *= a1; o[nt][3] *= a1;
        }

        // P -> per-warp-private smem strip (tf32-rounded)
#pragma unroll
        for (int nt = 0; nt < 8; nt++) {
            *(float2*)&Pr0[nt * 8 + 2 * lk] =
                make_float2(to_tf32(s[nt][0]), to_tf32(s[nt][1]));
            *(float2*)&Pr1[nt * 8 + 2 * lk] =
                make_float2(to_tf32(s[nt][2]), to_tf32(s[nt][3]));
        }
        __syncwarp();

        // O += P @ V   (V pitch 72: fragment LDS conflict-free)
#pragma unroll
        for (int ks = 0; ks < 8; ks++) {
            float ap[4];
            ap[0] = Pr0[ks * 8 + lk];
            ap[1] = Pr1[ks * 8 + lk];
            ap[2] = Pr0[ks * 8 + 4 + lk];
            ap[3] = Pr1[ks * 8 + 4 + lk];
#pragma unroll
            for (int nt = 0; nt < 8; nt++) {
                float b[2] = {cV[(ks * 8 + lk) * APV + nt * 8 + lr],
                              cV[(ks * 8 + 4 + lk) * APV + nt * 8 + lr]};
                mma_tf32(o[nt], ap, b);
            }
        }
        __syncwarp();
    }

    // Epilogue: normalize, tf32-round (feeds tf32 proj GEMM), write [B,T,C]
    const float inv0 = 1.f / l0;
    const float inv1 = 1.f / l1;
    const int b = bh >> 4;
    const int h = bh & 15;
    float* y0 = g_y + ((size_t)(b * SEQ + row0)) * CDIM + h * 64;
    float* y1 = g_y + ((size_t)(b * SEQ + row1)) * CDIM + h * 64;
#pragma unroll
    for (int nt = 0; nt < 8; nt++) {
        int d = nt * 8 + 2 * lk;
        *(float2*)(y0 + d) = make_float2(to_tf32(o[nt][0] * inv0),
                                         to_tf32(o[nt][1] * inv0));
        *(float2*)(y1 + d) = make_float2(to_tf32(o[nt][2] * inv1),
                                         to_tf32(o[nt][3] * inv1));
    }
}

// ---------------------------------------------------------------------------
extern "C" void kernel_launch(void* const* d_in, const int* in_sizes, int n_in,
                              void* d_out, int out_size)
{
    const float* x      = (const float*)d_in[0];
    const float* w_attn = (const float*)d_in[1];
    const float* b_attn = (const float*)d_in[2];
    const float* w_proj = (const float*)d_in[3];
    const float* b_proj = (const float*)d_in[4];
    float* out = (float*)d_out;

    cudaFuncSetAttribute(attn_mma, cudaFuncAttributeMaxDynamicSharedMemorySize,
                         SMEM_ATTN);
    cudaFuncSetAttribute(gemm_mma<true>, cudaFuncAttributeMaxDynamicSharedMemorySize,
                         GEMM_SMEM);
    cudaFuncSetAttribute(gemm_mma<false>, cudaFuncAttributeMaxDynamicSharedMemorySize,
                         GEMM_SMEM);

    void* y_ptr = nullptr;   cudaGetSymbolAddress(&y_ptr, g_y);
    void* xr_ptr = nullptr;  cudaGetSymbolAddress(&xr_ptr, g_xr);
    void* wt1_ptr = nullptr; cudaGetSymbolAddress(&wt1_ptr, g_wt1);
    void* wt2_ptr = nullptr; cudaGetSymbolAddress(&wt2_ptr, g_wt2);

    // 0) tf32-round x; transpose + round weights
    round_copy<<<(MROWS * CDIM / 4) / 256, 256>>>(x, (float*)xr_ptr);
    transpose_round<<<dim3(3072 / 32, 1024 / 32), dim3(32, 8)>>>(w_attn, (float*)wt1_ptr, 3072);
    transpose_round<<<dim3(1024 / 32, 1024 / 32), dim3(32, 8)>>>(w_proj, (float*)wt2_ptr, 1024);

    // 1) QKV projection (tf32 mma) + scatter to [BH][T][D]
    gemm_mma<true><<<dim3(3072 / 128, MROWS / 128), 128, GEMM_SMEM>>>(
        (const float*)xr_ptr, (const float*)wt1_ptr, b_attn, nullptr);

    // 2) Causal flash attention (tf32 mma)
    attn_mma<<<dim3(SEQ / 128, BH), 256, SMEM_ATTN>>>();

    // 3) Output projection (tf32 mma)
    gemm_mma<false><<<dim3(1024 / 128, MROWS / 128), 128, GEMM_SMEM>>>(
        (const float*)y_ptr, (const float*)wt2_ptr, b_proj, out);
}

// round 11
// speedup vs baseline: 2.8284x; 1.8069x over previous
#include <cuda_runtime.h>
#include <cuda_fp16.h>
#include <cstdint>

// Problem constants
#define BATCH   4
#define SEQ     2048
#define CDIM    1024
#define NHEAD   16
#define DHEAD   64
#define MROWS   (BATCH * SEQ)          // 8192
#define BH      (BATCH * NHEAD)        // 64

// Scratch (device globals; no allocations allowed)
__device__ __half g_q[(size_t)BH * SEQ * DHEAD];   // [BH][T][D], q pre-scaled
__device__ __half g_k[(size_t)BH * SEQ * DHEAD];
__device__ __half g_v[(size_t)BH * SEQ * DHEAD];
__device__ __half g_xh[(size_t)MROWS * CDIM];      // x, fp16
__device__ __half g_yh[(size_t)MROWS * CDIM];      // attn out, fp16 [B,T,C]
__device__ __half g_wt1[(size_t)3072 * 1024];      // w_attn^T, fp16
__device__ __half g_wt2[(size_t)1024 * 1024];      // w_proj^T, fp16

// ---------------------------------------------------------------------------
// Helpers
// ---------------------------------------------------------------------------
__device__ __forceinline__ uint32_t smem_u32(const void* p) {
    uint32_t a;
    asm("{ .reg .u64 t; cvta.to.shared.u64 t, %1; cvt.u32.u64 %0, t; }" : "=r"(a) : "l"(p));
    return a;
}
__device__ __forceinline__ void cp16(uint32_t smem_dst, const void* gsrc) {
    asm volatile("cp.async.cg.shared.global [%0], [%1], 16;" :: "r"(smem_dst), "l"(gsrc));
}
#define CP_COMMIT() asm volatile("cp.async.commit_group;" ::: "memory")
#define CP_WAIT(N)  asm volatile("cp.async.wait_group %0;" :: "n"(N) : "memory")

// m16n8k16 fp16 MMA (row.col), fp32 accumulate
__device__ __forceinline__ void mma_f16(float c[4], const uint32_t a[4],
                                        uint32_t b0, uint32_t b1) {
    asm volatile(
        "mma.sync.aligned.m16n8k16.row.col.f32.f16.f16.f32 "
        "{%0,%1,%2,%3}, {%4,%5,%6,%7}, {%8,%9}, {%0,%1,%2,%3};\n"
        : "+f"(c[0]), "+f"(c[1]), "+f"(c[2]), "+f"(c[3])
        : "r"(a[0]), "r"(a[1]), "r"(a[2]), "r"(a[3]), "r"(b0), "r"(b1));
}

// ldmatrix x4 transposed (b16)
__device__ __forceinline__ void ldsm4t(uint32_t& r0, uint32_t& r1,
                                       uint32_t& r2, uint32_t& r3, uint32_t addr) {
    asm volatile("ldmatrix.sync.aligned.m8n8.x4.trans.shared.b16 {%0,%1,%2,%3}, [%4];"
                 : "=r"(r0), "=r"(r1), "=r"(r2), "=r"(r3) : "r"(addr));
}

__device__ __forceinline__ uint32_t h2_u32(float a, float b) {
    __half2 h = __floats2half2_rn(a, b);
    return *(uint32_t*)&h;
}

// ---------------------------------------------------------------------------
// Pre-pass kernels: fp32 -> fp16 (+transpose for weights)
// ---------------------------------------------------------------------------
__global__ __launch_bounds__(256)
void f2h_copy(const float* __restrict__ src, __half* __restrict__ dst)
{
    int i = blockIdx.x * blockDim.x + threadIdx.x;
    float4 v = ((const float4*)src)[i];
    uint2 o;
    o.x = h2_u32(v.x, v.y);
    o.y = h2_u32(v.z, v.w);
    ((uint2*)dst)[i] = o;
}

__global__ __launch_bounds__(256)
void transpose_h(const float* __restrict__ W, __half* __restrict__ WT, int N)
{
    __shared__ float tile[32][33];
    int n0 = blockIdx.x * 32;
    int k0 = blockIdx.y * 32;
    int tx = threadIdx.x, ty = threadIdx.y;     // 32 x 8
#pragma unroll
    for (int i = ty; i < 32; i += 8)
        tile[i][tx] = W[(size_t)(k0 + i) * N + n0 + tx];
    __syncthreads();
#pragma unroll
    for (int i = ty; i < 32; i += 8)
        WT[(size_t)(n0 + i) * 1024 + k0 + tx] = __float2half(tile[tx][i]);
}

// ---------------------------------------------------------------------------
// fp16 mma.sync GEMM: out[M,N] = A[M,1024] @ W[1024,N] + bias
// 128x128 CTA tile, 4 warps of 64x64 output each, BK=32 (2 k-steps of 16),
// 3-stage cp.async pipeline, one __syncthreads per slab.
// Smem half tiles pitch 40 (80B rows -> conflict-free fragment LDS).
// SCATTER: write fp16 q/k/v (q scaled by 0.125); else fp32 out.
// ---------------------------------------------------------------------------
#define PH 40
#define STG_H (128 * PH)                          // halves per matrix
#define GEMM_SMEM (3 * 2 * STG_H * 2)             // 61,440 B

template <bool SCATTER>
__global__ __launch_bounds__(128)
void gemm_mma(const __half* __restrict__ A, const __half* __restrict__ BT,
              const float* __restrict__ bias, float* __restrict__ out)
{
    extern __shared__ __half smh[];

    const int tid = threadIdx.x;
    const int wid = tid >> 5;
    const int lane = tid & 31;
    const int wr = wid >> 1;
    const int wc = wid & 1;
    const int c0 = blockIdx.x * 128;
    const int r0 = blockIdx.y * 128;

    const __half* Ab = A + (size_t)r0 * 1024;
    const __half* Bb = BT + (size_t)c0 * 1024;

    float acc[4][8][4];
#pragma unroll
    for (int mt = 0; mt < 4; mt++)
#pragma unroll
        for (int nt = 0; nt < 8; nt++)
#pragma unroll
            for (int u = 0; u < 4; u++) acc[mt][nt][u] = 0.f;

    auto stage = [&](int c, int st) {
        __half* sA = smh + st * 2 * STG_H;
        __half* sB = sA + STG_H;
        const int k0 = c * 32;
#pragma unroll
        for (int i = 0; i < 4; i++) {
            int slot = tid + i * 128;        // 0..511
            int row = slot >> 2;             // 0..127
            int kq = (slot & 3) * 8;         // 0,8,16,24 halves
            cp16(smem_u32(&sA[row * PH + kq]),
                 Ab + (size_t)row * 1024 + k0 + kq);
            cp16(smem_u32(&sB[row * PH + kq]),
                 Bb + (size_t)row * 1024 + k0 + kq);
        }
        CP_COMMIT();
    };

    stage(0, 0);
    stage(1, 1);

    const int lr = lane >> 2;
    const int lk = lane & 3;

    for (int c = 0; c < 32; c++) {
        const int st = c % 3;
        CP_WAIT(1);
        __syncthreads();
        if (c + 2 < 32) stage(c + 2, (c + 2) % 3);
        else CP_COMMIT();

        const __half* tA = smh + st * 2 * STG_H + wr * 64 * PH;
        const __half* tB = smh + st * 2 * STG_H + STG_H + wc * 64 * PH;
#pragma unroll
        for (int ks = 0; ks < 2; ks++) {
            uint32_t b[8][2];
#pragma unroll
            for (int nt = 0; nt < 8; nt++) {
                const __half* Bn = &tB[(nt * 8 + lr) * PH + ks * 16 + 2 * lk];
                b[nt][0] = *(const uint32_t*)Bn;
                b[nt][1] = *(const uint32_t*)(Bn + 8);
            }
#pragma unroll
            for (int mt = 0; mt < 4; mt++) {
                const __half* Am = &tA[(mt * 16 + lr) * PH + ks * 16 + 2 * lk];
                uint32_t a[4];
                a[0] = *(const uint32_t*)Am;
                a[1] = *(const uint32_t*)(Am + 8 * PH);
                a[2] = *(const uint32_t*)(Am + 8);
                a[3] = *(const uint32_t*)(Am + 8 * PH + 8);
#pragma unroll
                for (int nt = 0; nt < 8; nt++)
                    mma_f16(acc[mt][nt], a, b[nt][0], b[nt][1]);
            }
        }
    }

    const int lc = (lane & 3) * 2;
#pragma unroll
    for (int mt = 0; mt < 4; mt++) {
#pragma unroll
        for (int nt = 0; nt < 8; nt++) {
            int m = r0 + wr * 64 + mt * 16 + lr;
            int n = c0 + wc * 64 + nt * 8 + lc;
            float b0 = bias[n], b1 = bias[n + 1];
            float v00 = acc[mt][nt][0] + b0, v01 = acc[mt][nt][1] + b1;
            float v10 = acc[mt][nt][2] + b0, v11 = acc[mt][nt][3] + b1;
            if (SCATTER) {
                int which = n >> 10;
                int cc = n & 1023;
                int h = cc >> 6;
                int d = cc & 63;
                int bb = m >> 11;
                int t = m & 2047;
                if (which == 0) {      // fold 1/sqrt(D) into q
                    v00 *= 0.125f; v01 *= 0.125f; v10 *= 0.125f; v11 *= 0.125f;
                }
                __half* dst = (which == 0) ? g_q : (which == 1) ? g_k : g_v;
                size_t base = (size_t)(bb * NHEAD + h) * SEQ;
                *(uint32_t*)(dst + (base + t) * DHEAD + d) = h2_u32(v00, v01);
                *(uint32_t*)(dst + (base + t + 8) * DHEAD + d) = h2_u32(v10, v11);
            } else {
                *(float2*)(out + (size_t)m * 1024 + n) = make_float2(v00, v01);
                *(float2*)(out + (size_t)(m + 8) * 1024 + n) = make_float2(v10, v11);
            }
        }
    }
}

// ---------------------------------------------------------------------------
// fp16 tensor-core flash attention (m16n8k16, fp32 softmax/accum)
// grid (16, 64): one CTA per (128-row Q tile, bh). 8 warps x 16 Q rows.
// K/V natural [s][d] half tiles (pitch 72 halves = 144B). PV B-frags via
// ldmatrix.x4.trans. 3-buffer cp.async pipeline, one __syncthreads per tile.
// P strip pitch 72 halves (rows span 64 cols — MUST exceed 64).
// ---------------------------------------------------------------------------
#define PHK 72
#define PHP 72
#define KBUFH (64 * PHK)
#define SMEM_ATTN ((6 * KBUFH + 128 * PHP) * 2)   // 73,728 B

__global__ __launch_bounds__(256)
void attn_mma()
{
    extern __shared__ __half smah[];
    __half* sK[3] = {smah, smah + KBUFH, smah + 2 * KBUFH};
    __half* sV[3] = {smah + 3 * KBUFH, smah + 4 * KBUFH, smah + 5 * KBUFH};
    __half* sP = smah + 6 * KBUFH;            // [128][PHP] per-warp-private

    const int qi = (int)gridDim.x - 1 - (int)blockIdx.x;   // heavy tiles first
    const int bh = blockIdx.y;
    const int tid = threadIdx.x;
    const int wid = tid >> 5;
    const int lane = tid & 31;
    const int lr = lane >> 2;        // 0..7
    const int lk = lane & 3;         // 0..3
    const int warp_m = wid * 16;
    const int q0 = qi * 128;

    const __half* Kg = g_k + (size_t)bh * SEQ * DHEAD;
    const __half* Vg = g_v + (size_t)bh * SEQ * DHEAD;

    // stage K/V tile kt (64 rows x 64 halves each) into buffer b
    auto stage = [&](int kt, int b) {
        const int k0 = kt * 64;
#pragma unroll
        for (int i = 0; i < 2; i++) {
            int slot = tid + i * 256;        // 0..511
            int row = slot >> 3;             // 0..63
            int cq = (slot & 7) * 8;         // 0..56 halves
            cp16(smem_u32(&sK[b][row * PHK + cq]), Kg + (size_t)(k0 + row) * 64 + cq);
            cp16(smem_u32(&sV[b][row * PHK + cq]), Vg + (size_t)(k0 + row) * 64 + cq);
        }
        CP_COMMIT();
    };

    // Q fragments (q pre-scaled at QKV epilogue): 4 k-steps of 16
    uint32_t qf[4][4];
    {
        const __half* Qw = g_q + ((size_t)bh * SEQ + q0 + warp_m) * DHEAD;
#pragma unroll
        for (int ks = 0; ks < 4; ks++) {
            const __half* p = Qw + lr * 64 + ks * 16 + 2 * lk;
            qf[ks][0] = *(const uint32_t*)p;
            qf[ks][1] = *(const uint32_t*)(p + 8 * 64);
            qf[ks][2] = *(const uint32_t*)(p + 8);
            qf[ks][3] = *(const uint32_t*)(p + 8 * 64 + 8);
        }
    }

    float o[8][4];
#pragma unroll
    for (int nt = 0; nt < 8; nt++)
#pragma unroll
        for (int u = 0; u < 4; u++) o[nt][u] = 0.f;

    float m0 = -1e30f, m1 = -1e30f, l0 = 0.f, l1 = 0.f;
    const int row0 = q0 + warp_m + lr;
    const int row1 = row0 + 8;

    __half* Pr0 = &sP[(warp_m + lr) * PHP];
    __half* Pr1 = &sP[(warp_m + lr + 8) * PHP];

    const int nkt = (qi + 1) * 2;
    stage(0, 0);
    if (nkt > 1) stage(1, 1); else CP_COMMIT();

    for (int kt = 0; kt < nkt; kt++) {
        const int st = kt % 3;
        const int k0 = kt * 64;

        CP_WAIT(1);                  // tile kt resident (kt+1 pending)
        __syncthreads();             // visibility; all warps finished kt-1
        if (kt + 2 < nkt) stage(kt + 2, (kt + 2) % 3);
        else CP_COMMIT();

        if (k0 > q0 + warp_m + 15) continue;

        const __half* cK = sK[st];
        const __half* cV = sV[st];

        // S = Q K^T   (16 x 64 per warp), fp32 accum
        float s[8][4];
#pragma unroll
        for (int nt = 0; nt < 8; nt++)
#pragma unroll
            for (int u = 0; u < 4; u++) s[nt][u] = 0.f;

#pragma unroll
        for (int nt = 0; nt < 8; nt++) {
            const __half* Kn = &cK[(nt * 8 + lr) * PHK + 2 * lk];
#pragma unroll
            for (int ks = 0; ks < 4; ks++) {
                uint32_t b0 = *(const uint32_t*)(Kn + ks * 16);
                uint32_t b1 = *(const uint32_t*)(Kn + ks * 16 + 8);
                mma_f16(s[nt], qf[ks], b0, b1);
            }
        }

        // Causal mask + row max
        const bool need_mask = (k0 + 63 > row0);
        float rmax0 = -1e30f, rmax1 = -1e30f;
#pragma unroll
        for (int nt = 0; nt < 8; nt++) {
            if (need_mask) {
                const int cb = k0 + nt * 8 + 2 * lk;
                if (cb     > row0) s[nt][0] = -1e30f;
                if (cb + 1 > row0) s[nt][1] = -1e30f;
                if (cb     > row1) s[nt][2] = -1e30f;
                if (cb + 1 > row1) s[nt][3] = -1e30f;
            }
            rmax0 = fmaxf(rmax0, fmaxf(s[nt][0], s[nt][1]));
            rmax1 = fmaxf(rmax1, fmaxf(s[nt][2], s[nt][3]));
        }
        rmax0 = fmaxf(rmax0, __shfl_xor_sync(0xffffffffu, rmax0, 1));
        rmax0 = fmaxf(rmax0, __shfl_xor_sync(0xffffffffu, rmax0, 2));
        rmax1 = fmaxf(rmax1, __shfl_xor_sync(0xffffffffu, rmax1, 1));
        rmax1 = fmaxf(rmax1, __shfl_xor_sync(0xffffffffu, rmax1, 2));

        const float mn0 = fmaxf(m0, rmax0);
        const float mn1 = fmaxf(m1, rmax1);
        const float a0 = __expf(m0 - mn0);
        const float a1 = __expf(m1 - mn1);
        m0 = mn0; m1 = mn1;

        float rs0 = 0.f, rs1 = 0.f;
#pragma unroll
        for (int nt = 0; nt < 8; nt++) {
            s[nt][0] = __expf(s[nt][0] - mn0);
            s[nt][1] = __expf(s[nt][1] - mn0);
            s[nt][2] = __expf(s[nt][2] - mn1);
            s[nt][3] = __expf(s[nt][3] - mn1);
            rs0 += s[nt][0] + s[nt][1];
            rs1 += s[nt][2] + s[nt][3];
        }
        rs0 += __shfl_xor_sync(0xffffffffu, rs0, 1);
        rs0 += __shfl_xor_sync(0xffffffffu, rs0, 2);
        rs1 += __shfl_xor_sync(0xffffffffu, rs1, 1);
        rs1 += __shfl_xor_sync(0xffffffffu, rs1, 2);
        l0 = l0 * a0 + rs0;
        l1 = l1 * a1 + rs1;

#pragma unroll
        for (int nt = 0; nt < 8; nt++) {
            o[nt][0] *= a0; o[nt][1] *= a0;
            o[nt][2] *= a1; o[nt][3] *= a1;
        }

        // P -> per-warp-private strip as fp16
#pragma unroll
        for (int nt = 0; nt < 8; nt++) {
            *(uint32_t*)&Pr0[nt * 8 + 2 * lk] = h2_u32(s[nt][0], s[nt][1]);
            *(uint32_t*)&Pr1[nt * 8 + 2 * lk] = h2_u32(s[nt][2], s[nt][3]);
        }
        __syncwarp();

        // O += P @ V  (B-frags via ldmatrix.x4.trans on natural [s][d] V)
        const int sm_row = lane & 15;
        const int sm_col = (lane >> 4) * 8;
#pragma unroll
        for (int ks = 0; ks < 4; ks++) {
            uint32_t ap[4];
            ap[0] = *(const uint32_t*)&Pr0[ks * 16 + 2 * lk];
            ap[1] = *(const uint32_t*)&Pr1[ks * 16 + 2 * lk];
            ap[2] = *(const uint32_t*)&Pr0[ks * 16 + 2 * lk + 8];
            ap[3] = *(const uint32_t*)&Pr1[ks * 16 + 2 * lk + 8];
#pragma unroll
            for (int ntp = 0; ntp < 4; ntp++) {
                uint32_t r0, r1, r2, r3;
                ldsm4t(r0, r1, r2, r3,
                       smem_u32(&cV[(ks * 16 + sm_row) * PHK + ntp * 16 + sm_col]));
                mma_f16(o[2 * ntp],     ap, r0, r1);
                mma_f16(o[2 * ntp + 1], ap, r2, r3);
            }
        }
        __syncwarp();
    }

    // Epilogue: normalize, write y as fp16 [B,T,C]
    const float inv0 = 1.f / l0;
    const float inv1 = 1.f / l1;
    const int b = bh >> 4;
    const int h = bh & 15;
    __half* y0 = g_yh + ((size_t)(b * SEQ + row0)) * CDIM + h * 64;
    __half* y1 = g_yh + ((size_t)(b * SEQ + row1)) * CDIM + h * 64;
#pragma unroll
    for (int nt = 0; nt < 8; nt++) {
        int d = nt * 8 + 2 * lk;
        *(uint32_t*)(y0 + d) = h2_u32(o[nt][0] * inv0, o[nt][1] * inv0);
        *(uint32_t*)(y1 + d) = h2_u32(o[nt][2] * inv1, o[nt][3] * inv1);
    }
}

// ---------------------------------------------------------------------------
extern "C" void kernel_launch(void* const* d_in, const int* in_sizes, int n_in,
                              void* d_out, int out_size)
{
    const float* x      = (const float*)d_in[0];
    const float* w_attn = (const float*)d_in[1];
    const float* b_attn = (const float*)d_in[2];
    const float* w_proj = (const float*)d_in[3];
    const float* b_proj = (const float*)d_in[4];
    float* out = (float*)d_out;

    cudaFuncSetAttribute(attn_mma, cudaFuncAttributeMaxDynamicSharedMemorySize,
                         SMEM_ATTN);
    cudaFuncSetAttribute(gemm_mma<true>, cudaFuncAttributeMaxDynamicSharedMemorySize,
                         GEMM_SMEM);
    cudaFuncSetAttribute(gemm_mma<false>, cudaFuncAttributeMaxDynamicSharedMemorySize,
                         GEMM_SMEM);

    void* xh_ptr = nullptr;  cudaGetSymbolAddress(&xh_ptr, g_xh);
    void* yh_ptr = nullptr;  cudaGetSymbolAddress(&yh_ptr, g_yh);
    void* wt1_ptr = nullptr; cudaGetSymbolAddress(&wt1_ptr, g_wt1);
    void* wt2_ptr = nullptr; cudaGetSymbolAddress(&wt2_ptr, g_wt2);

    // 0) fp32 -> fp16 conversions (x; transposed weights)
    f2h_copy<<<(MROWS * CDIM / 4) / 256, 256>>>(x, (__half*)xh_ptr);
    transpose_h<<<dim3(3072 / 32, 1024 / 32), dim3(32, 8)>>>(w_attn, (__half*)wt1_ptr, 3072);
    transpose_h<<<dim3(1024 / 32, 1024 / 32), dim3(32, 8)>>>(w_proj, (__half*)wt2_ptr, 1024);

    // 1) QKV projection (fp16 mma) + scatter to [BH][T][D] (q scaled)
    gemm_mma<true><<<dim3(3072 / 128, MROWS / 128), 128, GEMM_SMEM>>>(
        (const __half*)xh_ptr, (const __half*)wt1_ptr, b_attn, nullptr);

    // 2) Causal flash attention (fp16 mma)
    attn_mma<<<dim3(SEQ / 128, BH), 256, SMEM_ATTN>>>();

    // 3) Output projection (fp16 mma)
    gemm_mma<false><<<dim3(1024 / 128, MROWS / 128), 128, GEMM_SMEM>>>(
        (const __half*)yh_ptr, (const __half*)wt2_ptr, b_proj, out);
}

// round 12
// speedup vs baseline: 3.0197x; 1.0676x over previous
#include <cuda_runtime.h>
#include <cuda_fp16.h>
#include <cstdint>

// Problem constants
#define BATCH   4
#define SEQ     2048
#define CDIM    1024
#define NHEAD   16
#define DHEAD   64
#define MROWS   (BATCH * SEQ)          // 8192
#define BH      (BATCH * NHEAD)        // 64

// Scratch (device globals; no allocations allowed)
__device__ __half g_q[(size_t)BH * SEQ * DHEAD];   // [BH][T][D], q pre-scaled
__device__ __half g_k[(size_t)BH * SEQ * DHEAD];
__device__ __half g_v[(size_t)BH * SEQ * DHEAD];
__device__ __half g_xh[(size_t)MROWS * CDIM];      // x, fp16
__device__ __half g_yh[(size_t)MROWS * CDIM];      // attn out, fp16 [B,T,C]
__device__ __half g_wt1[(size_t)3072 * 1024];      // w_attn^T, fp16
__device__ __half g_wt2[(size_t)1024 * 1024];      // w_proj^T, fp16

// ---------------------------------------------------------------------------
// Helpers
// ---------------------------------------------------------------------------
__device__ __forceinline__ uint32_t smem_u32(const void* p) {
    uint32_t a;
    asm("{ .reg .u64 t; cvta.to.shared.u64 t, %1; cvt.u32.u64 %0, t; }" : "=r"(a) : "l"(p));
    return a;
}
__device__ __forceinline__ void cp16(uint32_t smem_dst, const void* gsrc) {
    asm volatile("cp.async.cg.shared.global [%0], [%1], 16;" :: "r"(smem_dst), "l"(gsrc));
}
#define CP_COMMIT() asm volatile("cp.async.commit_group;" ::: "memory")
#define CP_WAIT(N)  asm volatile("cp.async.wait_group %0;" :: "n"(N) : "memory")

// m16n8k16 fp16 MMA (row.col), fp32 accumulate
__device__ __forceinline__ void mma_f16(float c[4], const uint32_t a[4],
                                        uint32_t b0, uint32_t b1) {
    asm volatile(
        "mma.sync.aligned.m16n8k16.row.col.f32.f16.f16.f32 "
        "{%0,%1,%2,%3}, {%4,%5,%6,%7}, {%8,%9}, {%0,%1,%2,%3};\n"
        : "+f"(c[0]), "+f"(c[1]), "+f"(c[2]), "+f"(c[3])
        : "r"(a[0]), "r"(a[1]), "r"(a[2]), "r"(a[3]), "r"(b0), "r"(b1));
}

// ldmatrix x4 (b16), non-transposed / transposed
__device__ __forceinline__ void ldsm4(uint32_t& r0, uint32_t& r1,
                                      uint32_t& r2, uint32_t& r3, uint32_t addr) {
    asm volatile("ldmatrix.sync.aligned.m8n8.x4.shared.b16 {%0,%1,%2,%3}, [%4];"
                 : "=r"(r0), "=r"(r1), "=r"(r2), "=r"(r3) : "r"(addr));
}
__device__ __forceinline__ void ldsm4t(uint32_t& r0, uint32_t& r1,
                                       uint32_t& r2, uint32_t& r3, uint32_t addr) {
    asm volatile("ldmatrix.sync.aligned.m8n8.x4.trans.shared.b16 {%0,%1,%2,%3}, [%4];"
                 : "=r"(r0), "=r"(r1), "=r"(r2), "=r"(r3) : "r"(addr));
}

__device__ __forceinline__ uint32_t h2_u32(float a, float b) {
    __half2 h = __floats2half2_rn(a, b);
    return *(uint32_t*)&h;
}

// ---------------------------------------------------------------------------
// Pre-pass kernels: fp32 -> fp16 (+transpose for weights)
// ---------------------------------------------------------------------------
__global__ __launch_bounds__(256)
void f2h_copy(const float* __restrict__ src, __half* __restrict__ dst)
{
    int i = blockIdx.x * blockDim.x + threadIdx.x;
    float4 v = ((const float4*)src)[i];
    uint2 o;
    o.x = h2_u32(v.x, v.y);
    o.y = h2_u32(v.z, v.w);
    ((uint2*)dst)[i] = o;
}

__global__ __launch_bounds__(256)
void transpose_h(const float* __restrict__ W, __half* __restrict__ WT, int N)
{
    __shared__ float tile[32][33];
    int n0 = blockIdx.x * 32;
    int k0 = blockIdx.y * 32;
    int tx = threadIdx.x, ty = threadIdx.y;     // 32 x 8
#pragma unroll
    for (int i = ty; i < 32; i += 8)
        tile[i][tx] = W[(size_t)(k0 + i) * N + n0 + tx];
    __syncthreads();
#pragma unroll
    for (int i = ty; i < 32; i += 8)
        WT[(size_t)(n0 + i) * 1024 + k0 + tx] = __float2half(tile[tx][i]);
}

// ---------------------------------------------------------------------------
// fp16 mma.sync GEMM: out[M,N] = A[M,1024] @ W[1024,N] + bias
// 128x128 CTA tile, 4 warps of 64x64 output each, BK=32 (2 k-steps of 16),
// 3-stage cp.async pipeline. ALL fragment loads via ldmatrix.x4.
// Smem half tiles pitch 40 (80B rows -> conflict-free ldmatrix).
// ---------------------------------------------------------------------------
#define PH 40
#define STG_H (128 * PH)                          // halves per matrix
#define GEMM_SMEM (3 * 2 * STG_H * 2)             // 61,440 B

template <bool SCATTER>
__global__ __launch_bounds__(128)
void gemm_mma(const __half* __restrict__ A, const __half* __restrict__ BT,
              const float* __restrict__ bias, float* __restrict__ out)
{
    extern __shared__ __half smh[];

    const int tid = threadIdx.x;
    const int wid = tid >> 5;
    const int lane = tid & 31;
    const int wr = wid >> 1;
    const int wc = wid & 1;
    const int c0 = blockIdx.x * 128;
    const int r0 = blockIdx.y * 128;

    const __half* Ab = A + (size_t)r0 * 1024;
    const __half* Bb = BT + (size_t)c0 * 1024;

    // ldmatrix lane geometry: g = matrix idx (0..3), r = row within matrix
    const int lg = lane >> 3;
    const int lrow = lane & 7;

    float acc[4][8][4];
#pragma unroll
    for (int mt = 0; mt < 4; mt++)
#pragma unroll
        for (int nt = 0; nt < 8; nt++)
#pragma unroll
            for (int u = 0; u < 4; u++) acc[mt][nt][u] = 0.f;

    auto stage = [&](int c, int st) {
        __half* sA = smh + st * 2 * STG_H;
        __half* sB = sA + STG_H;
        const int k0 = c * 32;
#pragma unroll
        for (int i = 0; i < 4; i++) {
            int slot = tid + i * 128;        // 0..511
            int row = slot >> 2;             // 0..127
            int kq = (slot & 3) * 8;         // 0,8,16,24 halves
            cp16(smem_u32(&sA[row * PH + kq]),
                 Ab + (size_t)row * 1024 + k0 + kq);
            cp16(smem_u32(&sB[row * PH + kq]),
                 Bb + (size_t)row * 1024 + k0 + kq);
        }
        CP_COMMIT();
    };

    stage(0, 0);
    stage(1, 1);

    for (int c = 0; c < 32; c++) {
        const int st = c % 3;
        CP_WAIT(1);
        __syncthreads();
        if (c + 2 < 32) stage(c + 2, (c + 2) % 3);
        else CP_COMMIT();

        const __half* tA = smh + st * 2 * STG_H + wr * 64 * PH;
        const __half* tB = smh + st * 2 * STG_H + STG_H + wc * 64 * PH;
#pragma unroll
        for (int ks = 0; ks < 2; ks++) {
            // B frags: 4 ldmatrix.x4, each covers an nt pair
            // matrix g: nt = 2*j + (g>>1), k-half = (g&1)
            uint32_t b[8][2];
#pragma unroll
            for (int j = 0; j < 4; j++) {
                int n = (2 * j + (lg >> 1)) * 8 + lrow;
                int k = ks * 16 + (lg & 1) * 8;
                ldsm4(b[2 * j][0], b[2 * j][1], b[2 * j + 1][0], b[2 * j + 1][1],
                      smem_u32(&tB[n * PH + k]));
            }
            // A frags + MMAs: matrix g: m-half = (g&1), k-half = (g>>1)
#pragma unroll
            for (int mt = 0; mt < 4; mt++) {
                uint32_t a[4];
                int m = mt * 16 + (lg & 1) * 8 + lrow;
                int k = ks * 16 + (lg >> 1) * 8;
                ldsm4(a[0], a[1], a[2], a[3], smem_u32(&tA[m * PH + k]));
#pragma unroll
                for (int nt = 0; nt < 8; nt++)
                    mma_f16(acc[mt][nt], a, b[nt][0], b[nt][1]);
            }
        }
    }

    const int lr = lane >> 2;
    const int lc = (lane & 3) * 2;
#pragma unroll
    for (int mt = 0; mt < 4; mt++) {
#pragma unroll
        for (int nt = 0; nt < 8; nt++) {
            int m = r0 + wr * 64 + mt * 16 + lr;
            int n = c0 + wc * 64 + nt * 8 + lc;
            float b0 = bias[n], b1 = bias[n + 1];
            float v00 = acc[mt][nt][0] + b0, v01 = acc[mt][nt][1] + b1;
            float v10 = acc[mt][nt][2] + b0, v11 = acc[mt][nt][3] + b1;
            if (SCATTER) {
                int which = n >> 10;
                int cc = n & 1023;
                int h = cc >> 6;
                int d = cc & 63;
                int bb = m >> 11;
                int t = m & 2047;
                if (which == 0) {      // fold 1/sqrt(D) into q
                    v00 *= 0.125f; v01 *= 0.125f; v10 *= 0.125f; v11 *= 0.125f;
                }
                __half* dst = (which == 0) ? g_q : (which == 1) ? g_k : g_v;
                size_t base = (size_t)(bb * NHEAD + h) * SEQ;
                *(uint32_t*)(dst + (base + t) * DHEAD + d) = h2_u32(v00, v01);
                *(uint32_t*)(dst + (base + t + 8) * DHEAD + d) = h2_u32(v10, v11);
            } else {
                *(float2*)(out + (size_t)m * 1024 + n) = make_float2(v00, v01);
                *(float2*)(out + (size_t)(m + 8) * 1024 + n) = make_float2(v10, v11);
            }
        }
    }
}

// ---------------------------------------------------------------------------
// fp16 tensor-core flash attention (m16n8k16, fp32 softmax/accum)
// grid (16, 64): one CTA per (128-row Q tile, bh). 8 warps x 16 Q rows.
// K/V natural [s][d] half tiles (pitch 72 halves = 144B). All smem fragment
// loads via ldmatrix.x4 (K: non-trans, V: trans, P: non-trans).
// 3-buffer cp.async pipeline, one __syncthreads per tile.
// ---------------------------------------------------------------------------
#define PHK 72
#define PHP 72
#define KBUFH (64 * PHK)
#define SMEM_ATTN ((6 * KBUFH + 128 * PHP) * 2)   // 73,728 B

__global__ __launch_bounds__(256)
void attn_mma()
{
    extern __shared__ __half smah[];
    __half* sK[3] = {smah, smah + KBUFH, smah + 2 * KBUFH};
    __half* sV[3] = {smah + 3 * KBUFH, smah + 4 * KBUFH, smah + 5 * KBUFH};
    __half* sP = smah + 6 * KBUFH;            // [128][PHP] per-warp-private

    const int qi = (int)gridDim.x - 1 - (int)blockIdx.x;   // heavy tiles first
    const int bh = blockIdx.y;
    const int tid = threadIdx.x;
    const int wid = tid >> 5;
    const int lane = tid & 31;
    const int lr = lane >> 2;        // 0..7
    const int lk = lane & 3;         // 0..3
    const int lg = lane >> 3;        // ldmatrix matrix idx
    const int lrow = lane & 7;       // ldmatrix row
    const int warp_m = wid * 16;
    const int q0 = qi * 128;

    const __half* Kg = g_k + (size_t)bh * SEQ * DHEAD;
    const __half* Vg = g_v + (size_t)bh * SEQ * DHEAD;

    // stage K/V tile kt (64 rows x 64 halves each) into buffer b
    auto stage = [&](int kt, int b) {
        const int k0 = kt * 64;
#pragma unroll
        for (int i = 0; i < 2; i++) {
            int slot = tid + i * 256;        // 0..511
            int row = slot >> 3;             // 0..63
            int cq = (slot & 7) * 8;         // 0..56 halves
            cp16(smem_u32(&sK[b][row * PHK + cq]), Kg + (size_t)(k0 + row) * 64 + cq);
            cp16(smem_u32(&sV[b][row * PHK + cq]), Vg + (size_t)(k0 + row) * 64 + cq);
        }
        CP_COMMIT();
    };

    // Q fragments (q pre-scaled at QKV epilogue): 4 k-steps of 16
    uint32_t qf[4][4];
    {
        const __half* Qw = g_q + ((size_t)bh * SEQ + q0 + warp_m) * DHEAD;
#pragma unroll
        for (int ks = 0; ks < 4; ks++) {
            const __half* p = Qw + lr * 64 + ks * 16 + 2 * lk;
            qf[ks][0] = *(const uint32_t*)p;
            qf[ks][1] = *(const uint32_t*)(p + 8 * 64);
            qf[ks][2] = *(const uint32_t*)(p + 8);
            qf[ks][3] = *(const uint32_t*)(p + 8 * 64 + 8);
        }
    }

    float o[8][4];
#pragma unroll
    for (int nt = 0; nt < 8; nt++)
#pragma unroll
        for (int u = 0; u < 4; u++) o[nt][u] = 0.f;

    float m0 = -1e30f, m1 = -1e30f, l0 = 0.f, l1 = 0.f;
    const int row0 = q0 + warp_m + lr;
    const int row1 = row0 + 8;

    __half* Pr0 = &sP[(warp_m + lr) * PHP];
    __half* Pr1 = &sP[(warp_m + lr + 8) * PHP];

    const int nkt = (qi + 1) * 2;
    stage(0, 0);
    if (nkt > 1) stage(1, 1); else CP_COMMIT();

    for (int kt = 0; kt < nkt; kt++) {
        const int st = kt % 3;
        const int k0 = kt * 64;

        CP_WAIT(1);                  // tile kt resident (kt+1 pending)
        __syncthreads();             // visibility; all warps finished kt-1
        if (kt + 2 < nkt) stage(kt + 2, (kt + 2) % 3);
        else CP_COMMIT();

        if (k0 > q0 + warp_m + 15) continue;

        const __half* cK = sK[st];
        const __half* cV = sV[st];

        // S = Q K^T   (16 x 64 per warp), fp32 accum
        float s[8][4];
#pragma unroll
        for (int nt = 0; nt < 8; nt++)
#pragma unroll
            for (int u = 0; u < 4; u++) s[nt][u] = 0.f;

#pragma unroll
        for (int ks = 0; ks < 4; ks++) {
            // K B-frags: 4 ldmatrix.x4 per ks (nt pairs)
            uint32_t b[8][2];
#pragma unroll
            for (int j = 0; j < 4; j++) {
                int n = (2 * j + (lg >> 1)) * 8 + lrow;
                int k = ks * 16 + (lg & 1) * 8;
                ldsm4(b[2 * j][0], b[2 * j][1], b[2 * j + 1][0], b[2 * j + 1][1],
                      smem_u32(&cK[n * PHK + k]));
            }
#pragma unroll
            for (int nt = 0; nt < 8; nt++)
                mma_f16(s[nt], qf[ks], b[nt][0], b[nt][1]);
        }

        // Causal mask + row max
        const bool need_mask = (k0 + 63 > row0);
        float rmax0 = -1e30f, rmax1 = -1e30f;
#pragma unroll
        for (int nt = 0; nt < 8; nt++) {
            if (need_mask) {
                const int cb = k0 + nt * 8 + 2 * lk;
                if (cb     > row0) s[nt][0] = -1e30f;
                if (cb + 1 > row0) s[nt][1] = -1e30f;
                if (cb     > row1) s[nt][2] = -1e30f;
                if (cb + 1 > row1) s[nt][3] = -1e30f;
            }
            rmax0 = fmaxf(rmax0, fmaxf(s[nt][0], s[nt][1]));
            rmax1 = fmaxf(rmax1, fmaxf(s[nt][2], s[nt][3]));
        }
        rmax0 = fmaxf(rmax0, __shfl_xor_sync(0xffffffffu, rmax0, 1));
        rmax0 = fmaxf(rmax0, __shfl_xor_sync(0xffffffffu, rmax0, 2));
        rmax1 = fmaxf(rmax1, __shfl_xor_sync(0xffffffffu, rmax1, 1));
        rmax1 = fmaxf(rmax1, __shfl_xor_sync(0xffffffffu, rmax1, 2));

        const float mn0 = fmaxf(m0, rmax0);
        const float mn1 = fmaxf(m1, rmax1);
        const float a0 = __expf(m0 - mn0);
        const float a1 = __expf(m1 - mn1);
        m0 = mn0; m1 = mn1;

        float rs0 = 0.f, rs1 = 0.f;
#pragma unroll
        for (int nt = 0; nt < 8; nt++) {
            s[nt][0] = __expf(s[nt][0] - mn0);
            s[nt][1] = __expf(s[nt][1] - mn0);
            s[nt][2] = __expf(s[nt][2] - mn1);
            s[nt][3] = __expf(s[nt][3] - mn1);
            rs0 += s[nt][0] + s[nt][1];
            rs1 += s[nt][2] + s[nt][3];
        }
        rs0 += __shfl_xor_sync(0xffffffffu, rs0, 1);
        rs0 += __shfl_xor_sync(0xffffffffu, rs0, 2);
        rs1 += __shfl_xor_sync(0xffffffffu, rs1, 1);
        rs1 += __shfl_xor_sync(0xffffffffu, rs1, 2);
        l0 = l0 * a0 + rs0;
        l1 = l1 * a1 + rs1;

#pragma unroll
        for (int nt = 0; nt < 8; nt++) {
            o[nt][0] *= a0; o[nt][1] *= a0;
            o[nt][2] *= a1; o[nt][3] *= a1;
        }

        // P -> per-warp-private strip as fp16
#pragma unroll
        for (int nt = 0; nt < 8; nt++) {
            *(uint32_t*)&Pr0[nt * 8 + 2 * lk] = h2_u32(s[nt][0], s[nt][1]);
            *(uint32_t*)&Pr1[nt * 8 + 2 * lk] = h2_u32(s[nt][2], s[nt][3]);
        }
        __syncwarp();

        // O += P @ V  (P A-frags via ldmatrix.x4; V B-frags via ldmatrix.x4.trans)
        const int sm_row = lane & 15;
        const int sm_col = (lane >> 4) * 8;
        const __half* Pw = &sP[warp_m * PHP];
#pragma unroll
        for (int ks = 0; ks < 4; ks++) {
            uint32_t ap[4];
            {
                int m = (lg & 1) * 8 + lrow;
                int k = ks * 16 + (lg >> 1) * 8;
                ldsm4(ap[0], ap[1], ap[2], ap[3], smem_u32(&Pw[m * PHP + k]));
            }
#pragma unroll
            for (int ntp = 0; ntp < 4; ntp++) {
                uint32_t r0, r1, r2, r3;
                ldsm4t(r0, r1, r2, r3,
                       smem_u32(&cV[(ks * 16 + sm_row) * PHK + ntp * 16 + sm_col]));
                mma_f16(o[2 * ntp],     ap, r0, r1);
                mma_f16(o[2 * ntp + 1], ap, r2, r3);
            }
        }
        __syncwarp();
    }

    // Epilogue: normalize, write y as fp16 [B,T,C]
    const float inv0 = 1.f / l0;
    const float inv1 = 1.f / l1;
    const int b = bh >> 4;
    const int h = bh & 15;
    __half* y0 = g_yh + ((size_t)(b * SEQ + row0)) * CDIM + h * 64;
    __half* y1 = g_yh + ((size_t)(b * SEQ + row1)) * CDIM + h * 64;
#pragma unroll
    for (int nt = 0; nt < 8; nt++) {
        int d = nt * 8 + 2 * lk;
        *(uint32_t*)(y0 + d) = h2_u32(o[nt][0] * inv0, o[nt][1] * inv0);
        *(uint32_t*)(y1 + d) = h2_u32(o[nt][2] * inv1, o[nt][3] * inv1);
    }
}

// ---------------------------------------------------------------------------
extern "C" void kernel_launch(void* const* d_in, const int* in_sizes, int n_in,
                              void* d_out, int out_size)
{
    const float* x      = (const float*)d_in[0];
    const float* w_attn = (const float*)d_in[1];
    const float* b_attn = (const float*)d_in[2];
    const float* w_proj = (const float*)d_in[3];
    const float* b_proj = (const float*)d_in[4];
    float* out = (float*)d_out;

    cudaFuncSetAttribute(attn_mma, cudaFuncAttributeMaxDynamicSharedMemorySize,
                         SMEM_ATTN);
    cudaFuncSetAttribute(gemm_mma<true>, cudaFuncAttributeMaxDynamicSharedMemorySize,
                         GEMM_SMEM);
    cudaFuncSetAttribute(gemm_mma<false>, cudaFuncAttributeMaxDynamicSharedMemorySize,
                         GEMM_SMEM);

    void* xh_ptr = nullptr;  cudaGetSymbolAddress(&xh_ptr, g_xh);
    void* yh_ptr = nullptr;  cudaGetSymbolAddress(&yh_ptr, g_yh);
    void* wt1_ptr = nullptr; cudaGetSymbolAddress(&wt1_ptr, g_wt1);
    void* wt2_ptr = nullptr; cudaGetSymbolAddress(&wt2_ptr, g_wt2);

    // 0) fp32 -> fp16 conversions (x; transposed weights)
    f2h_copy<<<(MROWS * CDIM / 4) / 256, 256>>>(x, (__half*)xh_ptr);
    transpose_h<<<dim3(3072 / 32, 1024 / 32), dim3(32, 8)>>>(w_attn, (__half*)wt1_ptr, 3072);
    transpose_h<<<dim3(1024 / 32, 1024 / 32), dim3(32, 8)>>>(w_proj, (__half*)wt2_ptr, 1024);

    // 1) QKV projection (fp16 mma) + scatter to [BH][T][D] (q scaled)
    gemm_mma<true><<<dim3(3072 / 128, MROWS / 128), 128, GEMM_SMEM>>>(
        (const __half*)xh_ptr, (const __half*)wt1_ptr, b_attn, nullptr);

    // 2) Causal flash attention (fp16 mma)
    attn_mma<<<dim3(SEQ / 128, BH), 256, SMEM_ATTN>>>();

    // 3) Output projection (fp16 mma)
    gemm_mma<false><<<dim3(1024 / 128, MROWS / 128), 128, GEMM_SMEM>>>(
        (const __half*)yh_ptr, (const __half*)wt2_ptr, b_proj, out);
}

// round 13
// speedup vs baseline: 3.2490x; 1.0759x over previous
#include <cuda_runtime.h>
#include <cuda_fp16.h>
#include <cstdint>

// Problem constants
#define BATCH   4
#define SEQ     2048
#define CDIM    1024
#define NHEAD   16
#define DHEAD   64
#define MROWS   (BATCH * SEQ)          // 8192
#define BH      (BATCH * NHEAD)        // 64

// Scratch (device globals; no allocations allowed)
__device__ __half g_q[(size_t)BH * SEQ * DHEAD];   // [BH][T][D], q pre-scaled
__device__ __half g_k[(size_t)BH * SEQ * DHEAD];
__device__ __half g_v[(size_t)BH * SEQ * DHEAD];
__device__ __half g_xh[(size_t)MROWS * CDIM];      // x, fp16
__device__ __half g_yh[(size_t)MROWS * CDIM];      // attn out, fp16 [B,T,C]
__device__ __half g_wt1[(size_t)3072 * 1024];      // w_attn^T, fp16
__device__ __half g_wt2[(size_t)1024 * 1024];      // w_proj^T, fp16

// ---------------------------------------------------------------------------
// Helpers
// ---------------------------------------------------------------------------
__device__ __forceinline__ uint32_t smem_u32(const void* p) {
    uint32_t a;
    asm("{ .reg .u64 t; cvta.to.shared.u64 t, %1; cvt.u32.u64 %0, t; }" : "=r"(a) : "l"(p));
    return a;
}
__device__ __forceinline__ void cp16(uint32_t smem_dst, const void* gsrc) {
    asm volatile("cp.async.cg.shared.global [%0], [%1], 16;" :: "r"(smem_dst), "l"(gsrc));
}
#define CP_COMMIT() asm volatile("cp.async.commit_group;" ::: "memory")
#define CP_WAIT(N)  asm volatile("cp.async.wait_group %0;" :: "n"(N) : "memory")

// m16n8k16 fp16 MMA (row.col), fp32 accumulate
__device__ __forceinline__ void mma_f16(float c[4], const uint32_t a[4],
                                        uint32_t b0, uint32_t b1) {
    asm volatile(
        "mma.sync.aligned.m16n8k16.row.col.f32.f16.f16.f32 "
        "{%0,%1,%2,%3}, {%4,%5,%6,%7}, {%8,%9}, {%0,%1,%2,%3};\n"
        : "+f"(c[0]), "+f"(c[1]), "+f"(c[2]), "+f"(c[3])
        : "r"(a[0]), "r"(a[1]), "r"(a[2]), "r"(a[3]), "r"(b0), "r"(b1));
}

// ldmatrix x4 (b16), non-transposed / transposed
__device__ __forceinline__ void ldsm4(uint32_t& r0, uint32_t& r1,
                                      uint32_t& r2, uint32_t& r3, uint32_t addr) {
    asm volatile("ldmatrix.sync.aligned.m8n8.x4.shared.b16 {%0,%1,%2,%3}, [%4];"
                 : "=r"(r0), "=r"(r1), "=r"(r2), "=r"(r3) : "r"(addr));
}
__device__ __forceinline__ void ldsm4t(uint32_t& r0, uint32_t& r1,
                                       uint32_t& r2, uint32_t& r3, uint32_t addr) {
    asm volatile("ldmatrix.sync.aligned.m8n8.x4.trans.shared.b16 {%0,%1,%2,%3}, [%4];"
                 : "=r"(r0), "=r"(r1), "=r"(r2), "=r"(r3) : "r"(addr));
}

__device__ __forceinline__ uint32_t h2_u32(float a, float b) {
    __half2 h = __floats2half2_rn(a, b);
    return *(uint32_t*)&h;
}

// ---------------------------------------------------------------------------
// Pre-pass kernels: fp32 -> fp16 (+transpose for weights)
// ---------------------------------------------------------------------------
__global__ __launch_bounds__(256)
void f2h_copy(const float* __restrict__ src, __half* __restrict__ dst)
{
    int i = blockIdx.x * blockDim.x + threadIdx.x;
    float4 v = ((const float4*)src)[i];
    uint2 o;
    o.x = h2_u32(v.x, v.y);
    o.y = h2_u32(v.z, v.w);
    ((uint2*)dst)[i] = o;
}

__global__ __launch_bounds__(256)
void transpose_h(const float* __restrict__ W, __half* __restrict__ WT, int N)
{
    __shared__ float tile[32][33];
    int n0 = blockIdx.x * 32;
    int k0 = blockIdx.y * 32;
    int tx = threadIdx.x, ty = threadIdx.y;     // 32 x 8
#pragma unroll
    for (int i = ty; i < 32; i += 8)
        tile[i][tx] = W[(size_t)(k0 + i) * N + n0 + tx];
    __syncthreads();
#pragma unroll
    for (int i = ty; i < 32; i += 8)
        WT[(size_t)(n0 + i) * 1024 + k0 + tx] = __float2half(tile[tx][i]);
}

// ---------------------------------------------------------------------------
// fp16 mma.sync GEMM (exact R11 config — best measured):
// 128x128 CTA tile, 4 warps of 64x64 output each, BK=32 (2 k-steps of 16),
// 3-stage cp.async pipeline, one __syncthreads per slab.
// Scalar LDS.32 fragment loads (pitch 40 halves = 80B rows, conflict-free).
// ---------------------------------------------------------------------------
#define PH 40
#define STG_H (128 * PH)                          // halves per matrix
#define GEMM_SMEM (3 * 2 * STG_H * 2)             // 61,440 B

template <bool SCATTER>
__global__ __launch_bounds__(128)
void gemm_mma(const __half* __restrict__ A, const __half* __restrict__ BT,
              const float* __restrict__ bias, float* __restrict__ out)
{
    extern __shared__ __half smh[];

    const int tid = threadIdx.x;
    const int wid = tid >> 5;
    const int lane = tid & 31;
    const int wr = wid >> 1;
    const int wc = wid & 1;
    const int c0 = blockIdx.x * 128;
    const int r0 = blockIdx.y * 128;

    const __half* Ab = A + (size_t)r0 * 1024;
    const __half* Bb = BT + (size_t)c0 * 1024;

    float acc[4][8][4];
#pragma unroll
    for (int mt = 0; mt < 4; mt++)
#pragma unroll
        for (int nt = 0; nt < 8; nt++)
#pragma unroll
            for (int u = 0; u < 4; u++) acc[mt][nt][u] = 0.f;

    auto stage = [&](int c, int st) {
        __half* sA = smh + st * 2 * STG_H;
        __half* sB = sA + STG_H;
        const int k0 = c * 32;
#pragma unroll
        for (int i = 0; i < 4; i++) {
            int slot = tid + i * 128;        // 0..511
            int row = slot >> 2;             // 0..127
            int kq = (slot & 3) * 8;         // 0,8,16,24 halves
            cp16(smem_u32(&sA[row * PH + kq]),
                 Ab + (size_t)row * 1024 + k0 + kq);
            cp16(smem_u32(&sB[row * PH + kq]),
                 Bb + (size_t)row * 1024 + k0 + kq);
        }
        CP_COMMIT();
    };

    stage(0, 0);
    stage(1, 1);

    const int lr = lane >> 2;
    const int lk = lane & 3;

    for (int c = 0; c < 32; c++) {
        const int st = c % 3;
        CP_WAIT(1);
        __syncthreads();
        if (c + 2 < 32) stage(c + 2, (c + 2) % 3);
        else CP_COMMIT();

        const __half* tA = smh + st * 2 * STG_H + wr * 64 * PH;
        const __half* tB = smh + st * 2 * STG_H + STG_H + wc * 64 * PH;
#pragma unroll
        for (int ks = 0; ks < 2; ks++) {
            uint32_t b[8][2];
#pragma unroll
            for (int nt = 0; nt < 8; nt++) {
                const __half* Bn = &tB[(nt * 8 + lr) * PH + ks * 16 + 2 * lk];
                b[nt][0] = *(const uint32_t*)Bn;
                b[nt][1] = *(const uint32_t*)(Bn + 8);
            }
#pragma unroll
            for (int mt = 0; mt < 4; mt++) {
                const __half* Am = &tA[(mt * 16 + lr) * PH + ks * 16 + 2 * lk];
                uint32_t a[4];
                a[0] = *(const uint32_t*)Am;
                a[1] = *(const uint32_t*)(Am + 8 * PH);
                a[2] = *(const uint32_t*)(Am + 8);
                a[3] = *(const uint32_t*)(Am + 8 * PH + 8);
#pragma unroll
                for (int nt = 0; nt < 8; nt++)
                    mma_f16(acc[mt][nt], a, b[nt][0], b[nt][1]);
            }
        }
    }

    const int lc = (lane & 3) * 2;
#pragma unroll
    for (int mt = 0; mt < 4; mt++) {
#pragma unroll
        for (int nt = 0; nt < 8; nt++) {
            int m = r0 + wr * 64 + mt * 16 + lr;
            int n = c0 + wc * 64 + nt * 8 + lc;
            float b0 = bias[n], b1 = bias[n + 1];
            float v00 = acc[mt][nt][0] + b0, v01 = acc[mt][nt][1] + b1;
            float v10 = acc[mt][nt][2] + b0, v11 = acc[mt][nt][3] + b1;
            if (SCATTER) {
                int which = n >> 10;
                int cc = n & 1023;
                int h = cc >> 6;
                int d = cc & 63;
                int bb = m >> 11;
                int t = m & 2047;
                if (which == 0) {      // fold 1/sqrt(D) into q
                    v00 *= 0.125f; v01 *= 0.125f; v10 *= 0.125f; v11 *= 0.125f;
                }
                __half* dst = (which == 0) ? g_q : (which == 1) ? g_k : g_v;
                size_t base = (size_t)(bb * NHEAD + h) * SEQ;
                *(uint32_t*)(dst + (base + t) * DHEAD + d) = h2_u32(v00, v01);
                *(uint32_t*)(dst + (base + t + 8) * DHEAD + d) = h2_u32(v10, v11);
            } else {
                *(float2*)(out + (size_t)m * 1024 + n) = make_float2(v00, v01);
                *(float2*)(out + (size_t)(m + 8) * 1024 + n) = make_float2(v10, v11);
            }
        }
    }
}

// ---------------------------------------------------------------------------
// fp16 tensor-core flash attention (exact R12 config — best measured):
// m16n8k16, fp32 softmax/accum. grid (16, 64), 8 warps x 16 Q rows.
// K/V natural [s][d] (pitch 72 halves). All smem fragment loads via
// ldmatrix.x4 (K: non-trans, V: trans, P: non-trans).
// 3-buffer cp.async pipeline, one __syncthreads per tile.
// ---------------------------------------------------------------------------
#define PHK 72
#define PHP 72
#define KBUFH (64 * PHK)
#define SMEM_ATTN ((6 * KBUFH + 128 * PHP) * 2)   // 73,728 B

__global__ __launch_bounds__(256)
void attn_mma()
{
    extern __shared__ __half smah[];
    __half* sK[3] = {smah, smah + KBUFH, smah + 2 * KBUFH};
    __half* sV[3] = {smah + 3 * KBUFH, smah + 4 * KBUFH, smah + 5 * KBUFH};
    __half* sP = smah + 6 * KBUFH;            // [128][PHP] per-warp-private

    const int qi = (int)gridDim.x - 1 - (int)blockIdx.x;   // heavy tiles first
    const int bh = blockIdx.y;
    const int tid = threadIdx.x;
    const int wid = tid >> 5;
    const int lane = tid & 31;
    const int lr = lane >> 2;        // 0..7
    const int lk = lane & 3;         // 0..3
    const int lg = lane >> 3;        // ldmatrix matrix idx
    const int lrow = lane & 7;       // ldmatrix row
    const int warp_m = wid * 16;
    const int q0 = qi * 128;

    const __half* Kg = g_k + (size_t)bh * SEQ * DHEAD;
    const __half* Vg = g_v + (size_t)bh * SEQ * DHEAD;

    // stage K/V tile kt (64 rows x 64 halves each) into buffer b
    auto stage = [&](int kt, int b) {
        const int k0 = kt * 64;
#pragma unroll
        for (int i = 0; i < 2; i++) {
            int slot = tid + i * 256;        // 0..511
            int row = slot >> 3;             // 0..63
            int cq = (slot & 7) * 8;         // 0..56 halves
            cp16(smem_u32(&sK[b][row * PHK + cq]), Kg + (size_t)(k0 + row) * 64 + cq);
            cp16(smem_u32(&sV[b][row * PHK + cq]), Vg + (size_t)(k0 + row) * 64 + cq);
        }
        CP_COMMIT();
    };

    // Q fragments (q pre-scaled at QKV epilogue): 4 k-steps of 16
    uint32_t qf[4][4];
    {
        const __half* Qw = g_q + ((size_t)bh * SEQ + q0 + warp_m) * DHEAD;
#pragma unroll
        for (int ks = 0; ks < 4; ks++) {
            const __half* p = Qw + lr * 64 + ks * 16 + 2 * lk;
            qf[ks][0] = *(const uint32_t*)p;
            qf[ks][1] = *(const uint32_t*)(p + 8 * 64);
            qf[ks][2] = *(const uint32_t*)(p + 8);
            qf[ks][3] = *(const uint32_t*)(p + 8 * 64 + 8);
        }
    }

    float o[8][4];
#pragma unroll
    for (int nt = 0; nt < 8; nt++)
#pragma unroll
        for (int u = 0; u < 4; u++) o[nt][u] = 0.f;

    float m0 = -1e30f, m1 = -1e30f, l0 = 0.f, l1 = 0.f;
    const int row0 = q0 + warp_m + lr;
    const int row1 = row0 + 8;

    __half* Pr0 = &sP[(warp_m + lr) * PHP];
    __half* Pr1 = &sP[(warp_m + lr + 8) * PHP];

    const int nkt = (qi + 1) * 2;
    stage(0, 0);
    if (nkt > 1) stage(1, 1); else CP_COMMIT();

    for (int kt = 0; kt < nkt; kt++) {
        const int st = kt % 3;
        const int k0 = kt * 64;

        CP_WAIT(1);                  // tile kt resident (kt+1 pending)
        __syncthreads();             // visibility; all warps finished kt-1
        if (kt + 2 < nkt) stage(kt + 2, (kt + 2) % 3);
        else CP_COMMIT();

        if (k0 > q0 + warp_m + 15) continue;

        const __half* cK = sK[st];
        const __half* cV = sV[st];

        // S = Q K^T   (16 x 64 per warp), fp32 accum
        float s[8][4];
#pragma unroll
        for (int nt = 0; nt < 8; nt++)
#pragma unroll
            for (int u = 0; u < 4; u++) s[nt][u] = 0.f;

#pragma unroll
        for (int ks = 0; ks < 4; ks++) {
            // K B-frags: 4 ldmatrix.x4 per ks (nt pairs)
            uint32_t b[8][2];
#pragma unroll
            for (int j = 0; j < 4; j++) {
                int n = (2 * j + (lg >> 1)) * 8 + lrow;
                int k = ks * 16 + (lg & 1) * 8;
                ldsm4(b[2 * j][0], b[2 * j][1], b[2 * j + 1][0], b[2 * j + 1][1],
                      smem_u32(&cK[n * PHK + k]));
            }
#pragma unroll
            for (int nt = 0; nt < 8; nt++)
                mma_f16(s[nt], qf[ks], b[nt][0], b[nt][1]);
        }

        // Causal mask + row max
        const bool need_mask = (k0 + 63 > row0);
        float rmax0 = -1e30f, rmax1 = -1e30f;
#pragma unroll
        for (int nt = 0; nt < 8; nt++) {
            if (need_mask) {
                const int cb = k0 + nt * 8 + 2 * lk;
                if (cb     > row0) s[nt][0] = -1e30f;
                if (cb + 1 > row0) s[nt][1] = -1e30f;
                if (cb     > row1) s[nt][2] = -1e30f;
                if (cb + 1 > row1) s[nt][3] = -1e30f;
            }
            rmax0 = fmaxf(rmax0, fmaxf(s[nt][0], s[nt][1]));
            rmax1 = fmaxf(rmax1, fmaxf(s[nt][2], s[nt][3]));
        }
        rmax0 = fmaxf(rmax0, __shfl_xor_sync(0xffffffffu, rmax0, 1));
        rmax0 = fmaxf(rmax0, __shfl_xor_sync(0xffffffffu, rmax0, 2));
        rmax1 = fmaxf(rmax1, __shfl_xor_sync(0xffffffffu, rmax1, 1));
        rmax1 = fmaxf(rmax1, __shfl_xor_sync(0xffffffffu, rmax1, 2));

        const float mn0 = fmaxf(m0, rmax0);
        const float mn1 = fmaxf(m1, rmax1);
        const float a0 = __expf(m0 - mn0);
        const float a1 = __expf(m1 - mn1);
        m0 = mn0; m1 = mn1;

        float rs0 = 0.f, rs1 = 0.f;
#pragma unroll
        for (int nt = 0; nt < 8; nt++) {
            s[nt][0] = __expf(s[nt][0] - mn0);
            s[nt][1] = __expf(s[nt][1] - mn0);
            s[nt][2] = __expf(s[nt][2] - mn1);
            s[nt][3] = __expf(s[nt][3] - mn1);
            rs0 += s[nt][0] + s[nt][1];
            rs1 += s[nt][2] + s[nt][3];
        }
        rs0 += __shfl_xor_sync(0xffffffffu, rs0, 1);
        rs0 += __shfl_xor_sync(0xffffffffu, rs0, 2);
        rs1 += __shfl_xor_sync(0xffffffffu, rs1, 1);
        rs1 += __shfl_xor_sync(0xffffffffu, rs1, 2);
        l0 = l0 * a0 + rs0;
        l1 = l1 * a1 + rs1;

#pragma unroll
        for (int nt = 0; nt < 8; nt++) {
            o[nt][0] *= a0; o[nt][1] *= a0;
            o[nt][2] *= a1; o[nt][3] *= a1;
        }

        // P -> per-warp-private strip as fp16
#pragma unroll
        for (int nt = 0; nt < 8; nt++) {
            *(uint32_t*)&Pr0[nt * 8 + 2 * lk] = h2_u32(s[nt][0], s[nt][1]);
            *(uint32_t*)&Pr1[nt * 8 + 2 * lk] = h2_u32(s[nt][2], s[nt][3]);
        }
        __syncwarp();

        // O += P @ V  (P A-frags via ldmatrix.x4; V B-frags via ldmatrix.x4.trans)
        const int sm_row = lane & 15;
        const int sm_col = (lane >> 4) * 8;
        const __half* Pw = &sP[warp_m * PHP];
#pragma unroll
        for (int ks = 0; ks < 4; ks++) {
            uint32_t ap[4];
            {
                int m = (lg & 1) * 8 + lrow;
                int k = ks * 16 + (lg >> 1) * 8;
                ldsm4(ap[0], ap[1], ap[2], ap[3], smem_u32(&Pw[m * PHP + k]));
            }
#pragma unroll
            for (int ntp = 0; ntp < 4; ntp++) {
                uint32_t r0, r1, r2, r3;
                ldsm4t(r0, r1, r2, r3,
                       smem_u32(&cV[(ks * 16 + sm_row) * PHK + ntp * 16 + sm_col]));
                mma_f16(o[2 * ntp],     ap, r0, r1);
                mma_f16(o[2 * ntp + 1], ap, r2, r3);
            }
        }
        __syncwarp();
    }

    // Epilogue: normalize, write y as fp16 [B,T,C]
    const float inv0 = 1.f / l0;
    const float inv1 = 1.f / l1;
    const int b = bh >> 4;
    const int h = bh & 15;
    __half* y0 = g_yh + ((size_t)(b * SEQ + row0)) * CDIM + h * 64;
    __half* y1 = g_yh + ((size_t)(b * SEQ + row1)) * CDIM + h * 64;
#pragma unroll
    for (int nt = 0; nt < 8; nt++) {
        int d = nt * 8 + 2 * lk;
        *(uint32_t*)(y0 + d) = h2_u32(o[nt][0] * inv0, o[nt][1] * inv0);
        *(uint32_t*)(y1 + d) = h2_u32(o[nt][2] * inv1, o[nt][3] * inv1);
    }
}

// ---------------------------------------------------------------------------
extern "C" void kernel_launch(void* const* d_in, const int* in_sizes, int n_in,
                              void* d_out, int out_size)
{
    const float* x      = (const float*)d_in[0];
    const float* w_attn = (const float*)d_in[1];
    const float* b_attn = (const float*)d_in[2];
    const float* w_proj = (const float*)d_in[3];
    const float* b_proj = (const float*)d_in[4];
    float* out = (float*)d_out;

    cudaFuncSetAttribute(attn_mma, cudaFuncAttributeMaxDynamicSharedMemorySize,
                         SMEM_ATTN);
    cudaFuncSetAttribute(gemm_mma<true>, cudaFuncAttributeMaxDynamicSharedMemorySize,
                         GEMM_SMEM);
    cudaFuncSetAttribute(gemm_mma<false>, cudaFuncAttributeMaxDynamicSharedMemorySize,
                         GEMM_SMEM);

    void* xh_ptr = nullptr;  cudaGetSymbolAddress(&xh_ptr, g_xh);
    void* yh_ptr = nullptr;  cudaGetSymbolAddress(&yh_ptr, g_yh);
    void* wt1_ptr = nullptr; cudaGetSymbolAddress(&wt1_ptr, g_wt1);
    void* wt2_ptr = nullptr; cudaGetSymbolAddress(&wt2_ptr, g_wt2);

    // 0) fp32 -> fp16 conversions (x; transposed weights)
    f2h_copy<<<(MROWS * CDIM / 4) / 256, 256>>>(x, (__half*)xh_ptr);
    transpose_h<<<dim3(3072 / 32, 1024 / 32), dim3(32, 8)>>>(w_attn, (__half*)wt1_ptr, 3072);
    transpose_h<<<dim3(1024 / 32, 1024 / 32), dim3(32, 8)>>>(w_proj, (__half*)wt2_ptr, 1024);

    // 1) QKV projection (fp16 mma) + scatter to [BH][T][D] (q scaled)
    gemm_mma<true><<<dim3(3072 / 128, MROWS / 128), 128, GEMM_SMEM>>>(
        (const __half*)xh_ptr, (const __half*)wt1_ptr, b_attn, nullptr);

    // 2) Causal flash attention (fp16 mma)
    attn_mma<<<dim3(SEQ / 128, BH), 256, SMEM_ATTN>>>();

    // 3) Output projection (fp16 mma)
    gemm_mma<false><<<dim3(1024 / 128, MROWS / 128), 128, GEMM_SMEM>>>(
        (const __half*)yh_ptr, (const __half*)wt2_ptr, b_proj, out);
}

// round 14
// speedup vs baseline: 3.4871x; 1.0733x over previous
#include <cuda_runtime.h>
#include <cuda_fp16.h>
#include <cstdint>

// Problem constants
#define BATCH   4
#define SEQ     2048
#define CDIM    1024
#define NHEAD   16
#define DHEAD   64
#define MROWS   (BATCH * SEQ)          // 8192
#define BH      (BATCH * NHEAD)        // 64

// Scratch (device globals; no allocations allowed)
__device__ __half g_q[(size_t)BH * SEQ * DHEAD];   // [BH][T][D], q pre-scaled by 0.125*log2e
__device__ __half g_k[(size_t)BH * SEQ * DHEAD];
__device__ __half g_v[(size_t)BH * SEQ * DHEAD];
__device__ __half g_xh[(size_t)MROWS * CDIM];      // x, fp16
__device__ __half g_yh[(size_t)MROWS * CDIM];      // attn out, fp16 [B,T,C]
__device__ __half g_wt1[(size_t)3072 * 1024];      // w_attn^T, fp16
__device__ __half g_wt2[(size_t)1024 * 1024];      // w_proj^T, fp16

// ---------------------------------------------------------------------------
// Helpers
// ---------------------------------------------------------------------------
__device__ __forceinline__ uint32_t smem_u32(const void* p) {
    uint32_t a;
    asm("{ .reg .u64 t; cvta.to.shared.u64 t, %1; cvt.u32.u64 %0, t; }" : "=r"(a) : "l"(p));
    return a;
}
__device__ __forceinline__ void cp16(uint32_t smem_dst, const void* gsrc) {
    asm volatile("cp.async.cg.shared.global [%0], [%1], 16;" :: "r"(smem_dst), "l"(gsrc));
}
#define CP_COMMIT() asm volatile("cp.async.commit_group;" ::: "memory")
#define CP_WAIT(N)  asm volatile("cp.async.wait_group %0;" :: "n"(N) : "memory")

// m16n8k16 fp16 MMA (row.col), fp32 accumulate
__device__ __forceinline__ void mma_f16(float c[4], const uint32_t a[4],
                                        uint32_t b0, uint32_t b1) {
    asm volatile(
        "mma.sync.aligned.m16n8k16.row.col.f32.f16.f16.f32 "
        "{%0,%1,%2,%3}, {%4,%5,%6,%7}, {%8,%9}, {%0,%1,%2,%3};\n"
        : "+f"(c[0]), "+f"(c[1]), "+f"(c[2]), "+f"(c[3])
        : "r"(a[0]), "r"(a[1]), "r"(a[2]), "r"(a[3]), "r"(b0), "r"(b1));
}

// ldmatrix x4 (b16), non-transposed / transposed
__device__ __forceinline__ void ldsm4(uint32_t& r0, uint32_t& r1,
                                      uint32_t& r2, uint32_t& r3, uint32_t addr) {
    asm volatile("ldmatrix.sync.aligned.m8n8.x4.shared.b16 {%0,%1,%2,%3}, [%4];"
                 : "=r"(r0), "=r"(r1), "=r"(r2), "=r"(r3) : "r"(addr));
}
__device__ __forceinline__ void ldsm4t(uint32_t& r0, uint32_t& r1,
                                       uint32_t& r2, uint32_t& r3, uint32_t addr) {
    asm volatile("ldmatrix.sync.aligned.m8n8.x4.trans.shared.b16 {%0,%1,%2,%3}, [%4];"
                 : "=r"(r0), "=r"(r1), "=r"(r2), "=r"(r3) : "r"(addr));
}

__device__ __forceinline__ uint32_t h2_u32(float a, float b) {
    __half2 h = __floats2half2_rn(a, b);
    return *(uint32_t*)&h;
}

// ---------------------------------------------------------------------------
// Merged pre-pass: one launch covering
//   job 0: x  fp32->fp16          (8192 blocks)
//   job 1: w_attn transpose+cvt   (96*32 = 3072 blocks)
//   job 2: w_proj transpose+cvt   (32*32 = 1024 blocks)
// ---------------------------------------------------------------------------
#define PRE_BLOCKS (8192 + 3072 + 1024)

__global__ __launch_bounds__(256)
void prepass(const float* __restrict__ x,
             const float* __restrict__ w_attn,
             const float* __restrict__ w_proj,
             __half* __restrict__ xh,
             __half* __restrict__ wt1,
             __half* __restrict__ wt2)
{
    const int blk = blockIdx.x;
    const int tid = threadIdx.x;

    if (blk < 8192) {
        // f2h of x: float4 granularity
        int i = blk * 256 + tid;
        float4 v = ((const float4*)x)[i];
        uint2 o;
        o.x = h2_u32(v.x, v.y);
        o.y = h2_u32(v.z, v.w);
        ((uint2*)xh)[i] = o;
        return;
    }

    // transpose jobs
    __shared__ float tile[32][33];
    const float* W;
    __half* WT;
    int N, bx, by;
    if (blk < 8192 + 3072) {
        int idx = blk - 8192;
        W = w_attn; WT = wt1; N = 3072;
        bx = idx % 96; by = idx / 96;
    } else {
        int idx = blk - 8192 - 3072;
        W = w_proj; WT = wt2; N = 1024;
        bx = idx % 32; by = idx / 32;
    }
    int n0 = bx * 32;
    int k0 = by * 32;
    int tx = tid & 31, ty = tid >> 5;    // 32 x 8
#pragma unroll
    for (int i = ty; i < 32; i += 8)
        tile[i][tx] = W[(size_t)(k0 + i) * N + n0 + tx];
    __syncthreads();
#pragma unroll
    for (int i = ty; i < 32; i += 8)
        WT[(size_t)(n0 + i) * 1024 + k0 + tx] = __float2half(tile[tx][i]);
}

// ---------------------------------------------------------------------------
// fp16 mma.sync GEMM (R11/R13 config — best measured):
// 128x128 CTA tile, 4 warps of 64x64 output each, BK=32 (2 k-steps of 16),
// 3-stage cp.async pipeline, one __syncthreads per slab.
// Scalar LDS.32 fragment loads (pitch 40 halves = 80B rows, conflict-free).
// ---------------------------------------------------------------------------
#define PH 40
#define STG_H (128 * PH)                          // halves per matrix
#define GEMM_SMEM (3 * 2 * STG_H * 2)             // 61,440 B

template <bool SCATTER>
__global__ __launch_bounds__(128)
void gemm_mma(const __half* __restrict__ A, const __half* __restrict__ BT,
              const float* __restrict__ bias, float* __restrict__ out)
{
    extern __shared__ __half smh[];

    const int tid = threadIdx.x;
    const int wid = tid >> 5;
    const int lane = tid & 31;
    const int wr = wid >> 1;
    const int wc = wid & 1;
    const int c0 = blockIdx.x * 128;
    const int r0 = blockIdx.y * 128;

    const __half* Ab = A + (size_t)r0 * 1024;
    const __half* Bb = BT + (size_t)c0 * 1024;

    float acc[4][8][4];
#pragma unroll
    for (int mt = 0; mt < 4; mt++)
#pragma unroll
        for (int nt = 0; nt < 8; nt++)
#pragma unroll
            for (int u = 0; u < 4; u++) acc[mt][nt][u] = 0.f;

    auto stage = [&](int c, int st) {
        __half* sA = smh + st * 2 * STG_H;
        __half* sB = sA + STG_H;
        const int k0 = c * 32;
#pragma unroll
        for (int i = 0; i < 4; i++) {
            int slot = tid + i * 128;        // 0..511
            int row = slot >> 2;             // 0..127
            int kq = (slot & 3) * 8;         // 0,8,16,24 halves
            cp16(smem_u32(&sA[row * PH + kq]),
                 Ab + (size_t)row * 1024 + k0 + kq);
            cp16(smem_u32(&sB[row * PH + kq]),
                 Bb + (size_t)row * 1024 + k0 + kq);
        }
        CP_COMMIT();
    };

    stage(0, 0);
    stage(1, 1);

    const int lr = lane >> 2;
    const int lk = lane & 3;

    for (int c = 0; c < 32; c++) {
        const int st = c % 3;
        CP_WAIT(1);
        __syncthreads();
        if (c + 2 < 32) stage(c + 2, (c + 2) % 3);
        else CP_COMMIT();

        const __half* tA = smh + st * 2 * STG_H + wr * 64 * PH;
        const __half* tB = smh + st * 2 * STG_H + STG_H + wc * 64 * PH;
#pragma unroll
        for (int ks = 0; ks < 2; ks++) {
            uint32_t b[8][2];
#pragma unroll
            for (int nt = 0; nt < 8; nt++) {
                const __half* Bn = &tB[(nt * 8 + lr) * PH + ks * 16 + 2 * lk];
                b[nt][0] = *(const uint32_t*)Bn;
                b[nt][1] = *(const uint32_t*)(Bn + 8);
            }
#pragma unroll
            for (int mt = 0; mt < 4; mt++) {
                const __half* Am = &tA[(mt * 16 + lr) * PH + ks * 16 + 2 * lk];
                uint32_t a[4];
                a[0] = *(const uint32_t*)Am;
                a[1] = *(const uint32_t*)(Am + 8 * PH);
                a[2] = *(const uint32_t*)(Am + 8);
                a[3] = *(const uint32_t*)(Am + 8 * PH + 8);
#pragma unroll
                for (int nt = 0; nt < 8; nt++)
                    mma_f16(acc[mt][nt], a, b[nt][0], b[nt][1]);
            }
        }
    }

    const int lc = (lane & 3) * 2;
#pragma unroll
    for (int mt = 0; mt < 4; mt++) {
#pragma unroll
        for (int nt = 0; nt < 8; nt++) {
            int m = r0 + wr * 64 + mt * 16 + lr;
            int n = c0 + wc * 64 + nt * 8 + lc;
            float b0 = bias[n], b1 = bias[n + 1];
            float v00 = acc[mt][nt][0] + b0, v01 = acc[mt][nt][1] + b1;
            float v10 = acc[mt][nt][2] + b0, v11 = acc[mt][nt][3] + b1;
            if (SCATTER) {
                int which = n >> 10;
                int cc = n & 1023;
                int h = cc >> 6;
                int d = cc & 63;
                int bb = m >> 11;
                int t = m & 2047;
                if (which == 0) {
                    // fold 1/sqrt(D) * log2(e) into q (attention uses exp2)
                    const float qs = 0.125f * 1.44269504089f;
                    v00 *= qs; v01 *= qs; v10 *= qs; v11 *= qs;
                }
                __half* dst = (which == 0) ? g_q : (which == 1) ? g_k : g_v;
                size_t base = (size_t)(bb * NHEAD + h) * SEQ;
                *(uint32_t*)(dst + (base + t) * DHEAD + d) = h2_u32(v00, v01);
                *(uint32_t*)(dst + (base + t + 8) * DHEAD + d) = h2_u32(v10, v11);
            } else {
                *(float2*)(out + (size_t)m * 1024 + n) = make_float2(v00, v01);
                *(float2*)(out + (size_t)(m + 8) * 1024 + n) = make_float2(v10, v11);
            }
        }
    }
}

// ---------------------------------------------------------------------------
// fp16 tensor-core flash attention (m16n8k16, fp32 softmax/accum, exp2 domain)
// grid (16, 64), 8 warps x 16 Q rows. K/V natural [s][d] (pitch 72 halves).
// S accumulators repacked DIRECTLY into PV A-fragments (no P smem round-trip).
// V B-frags via ldmatrix.x4.trans. 3-buffer cp.async, one barrier per tile.
// ---------------------------------------------------------------------------
#define PHK 72
#define KBUFH (64 * PHK)
#define SMEM_ATTN (6 * KBUFH * 2)                 // 55,296 B

__global__ __launch_bounds__(256)
void attn_mma()
{
    extern __shared__ __half smah[];
    __half* sK[3] = {smah, smah + KBUFH, smah + 2 * KBUFH};
    __half* sV[3] = {smah + 3 * KBUFH, smah + 4 * KBUFH, smah + 5 * KBUFH};

    const int qi = (int)gridDim.x - 1 - (int)blockIdx.x;   // heavy tiles first
    const int bh = blockIdx.y;
    const int tid = threadIdx.x;
    const int wid = tid >> 5;
    const int lane = tid & 31;
    const int lr = lane >> 2;        // 0..7
    const int lk = lane & 3;         // 0..3
    const int lg = lane >> 3;        // ldmatrix matrix idx
    const int lrow = lane & 7;       // ldmatrix row
    const int warp_m = wid * 16;
    const int q0 = qi * 128;

    const __half* Kg = g_k + (size_t)bh * SEQ * DHEAD;
    const __half* Vg = g_v + (size_t)bh * SEQ * DHEAD;

    // stage K/V tile kt (64 rows x 64 halves each) into buffer b
    auto stage = [&](int kt, int b) {
        const int k0 = kt * 64;
#pragma unroll
        for (int i = 0; i < 2; i++) {
            int slot = tid + i * 256;        // 0..511
            int row = slot >> 3;             // 0..63
            int cq = (slot & 7) * 8;         // 0..56 halves
            cp16(smem_u32(&sK[b][row * PHK + cq]), Kg + (size_t)(k0 + row) * 64 + cq);
            cp16(smem_u32(&sV[b][row * PHK + cq]), Vg + (size_t)(k0 + row) * 64 + cq);
        }
        CP_COMMIT();
    };

    // Q fragments (pre-scaled by 0.125*log2e at QKV epilogue): 4 k-steps of 16
    uint32_t qf[4][4];
    {
        const __half* Qw = g_q + ((size_t)bh * SEQ + q0 + warp_m) * DHEAD;
#pragma unroll
        for (int ks = 0; ks < 4; ks++) {
            const __half* p = Qw + lr * 64 + ks * 16 + 2 * lk;
            qf[ks][0] = *(const uint32_t*)p;
            qf[ks][1] = *(const uint32_t*)(p + 8 * 64);
            qf[ks][2] = *(const uint32_t*)(p + 8);
            qf[ks][3] = *(const uint32_t*)(p + 8 * 64 + 8);
        }
    }

    float o[8][4];
#pragma unroll
    for (int nt = 0; nt < 8; nt++)
#pragma unroll
        for (int u = 0; u < 4; u++) o[nt][u] = 0.f;

    float m0 = -1e30f, m1 = -1e30f, l0 = 0.f, l1 = 0.f;
    const int row0 = q0 + warp_m + lr;
    const int row1 = row0 + 8;

    const int nkt = (qi + 1) * 2;
    stage(0, 0);
    if (nkt > 1) stage(1, 1); else CP_COMMIT();

    for (int kt = 0; kt < nkt; kt++) {
        const int st = kt % 3;
        const int k0 = kt * 64;

        CP_WAIT(1);                  // tile kt resident (kt+1 pending)
        __syncthreads();             // visibility; all warps finished kt-1
        if (kt + 2 < nkt) stage(kt + 2, (kt + 2) % 3);
        else CP_COMMIT();

        if (k0 > q0 + warp_m + 15) continue;

        const __half* cK = sK[st];
        const __half* cV = sV[st];

        // S = Q K^T   (16 x 64 per warp), fp32 accum (log2 domain)
        float s[8][4];
#pragma unroll
        for (int nt = 0; nt < 8; nt++)
#pragma unroll
            for (int u = 0; u < 4; u++) s[nt][u] = 0.f;

#pragma unroll
        for (int ks = 0; ks < 4; ks++) {
            uint32_t b[8][2];
#pragma unroll
            for (int j = 0; j < 4; j++) {
                int n = (2 * j + (lg >> 1)) * 8 + lrow;
                int k = ks * 16 + (lg & 1) * 8;
                ldsm4(b[2 * j][0], b[2 * j][1], b[2 * j + 1][0], b[2 * j + 1][1],
                      smem_u32(&cK[n * PHK + k]));
            }
#pragma unroll
            for (int nt = 0; nt < 8; nt++)
                mma_f16(s[nt], qf[ks], b[nt][0], b[nt][1]);
        }

        // Causal mask + row max
        const bool need_mask = (k0 + 63 > row0);
        float rmax0 = -1e30f, rmax1 = -1e30f;
#pragma unroll
        for (int nt = 0; nt < 8; nt++) {
            if (need_mask) {
                const int cb = k0 + nt * 8 + 2 * lk;
                if (cb     > row0) s[nt][0] = -1e30f;
                if (cb + 1 > row0) s[nt][1] = -1e30f;
                if (cb     > row1) s[nt][2] = -1e30f;
                if (cb + 1 > row1) s[nt][3] = -1e30f;
            }
            rmax0 = fmaxf(rmax0, fmaxf(s[nt][0], s[nt][1]));
            rmax1 = fmaxf(rmax1, fmaxf(s[nt][2], s[nt][3]));
        }
        rmax0 = fmaxf(rmax0, __shfl_xor_sync(0xffffffffu, rmax0, 1));
        rmax0 = fmaxf(rmax0, __shfl_xor_sync(0xffffffffu, rmax0, 2));
        rmax1 = fmaxf(rmax1, __shfl_xor_sync(0xffffffffu, rmax1, 1));
        rmax1 = fmaxf(rmax1, __shfl_xor_sync(0xffffffffu, rmax1, 2));

        const float mn0 = fmaxf(m0, rmax0);
        const float mn1 = fmaxf(m1, rmax1);
        const float a0 = exp2f(m0 - mn0);
        const float a1 = exp2f(m1 - mn1);
        m0 = mn0; m1 = mn1;

        float rs0 = 0.f, rs1 = 0.f;
#pragma unroll
        for (int nt = 0; nt < 8; nt++) {
            s[nt][0] = exp2f(s[nt][0] - mn0);
            s[nt][1] = exp2f(s[nt][1] - mn0);
            s[nt][2] = exp2f(s[nt][2] - mn1);
            s[nt][3] = exp2f(s[nt][3] - mn1);
            rs0 += s[nt][0] + s[nt][1];
            rs1 += s[nt][2] + s[nt][3];
        }
        rs0 += __shfl_xor_sync(0xffffffffu, rs0, 1);
        rs0 += __shfl_xor_sync(0xffffffffu, rs0, 2);
        rs1 += __shfl_xor_sync(0xffffffffu, rs1, 1);
        rs1 += __shfl_xor_sync(0xffffffffu, rs1, 2);
        l0 = l0 * a0 + rs0;
        l1 = l1 * a1 + rs1;

#pragma unroll
        for (int nt = 0; nt < 8; nt++) {
            o[nt][0] *= a0; o[nt][1] *= a0;
            o[nt][2] *= a1; o[nt][3] *= a1;
        }

        // O += P @ V
        // P A-frags are a DIRECT repack of the S accumulators:
        //   step ks covers S-tiles 2ks (cols 0..7) and 2ks+1 (cols 8..15).
        const int sm_row = lane & 15;
        const int sm_col = (lane >> 4) * 8;
#pragma unroll
        for (int ks = 0; ks < 4; ks++) {
            uint32_t ap[4];
            ap[0] = h2_u32(s[2 * ks][0],     s[2 * ks][1]);
            ap[1] = h2_u32(s[2 * ks][2],     s[2 * ks][3]);
            ap[2] = h2_u32(s[2 * ks + 1][0], s[2 * ks + 1][1]);
            ap[3] = h2_u32(s[2 * ks + 1][2], s[2 * ks + 1][3]);
#pragma unroll
            for (int ntp = 0; ntp < 4; ntp++) {
                uint32_t r0, r1, r2, r3;
                ldsm4t(r0, r1, r2, r3,
                       smem_u32(&cV[(ks * 16 + sm_row) * PHK + ntp * 16 + sm_col]));
                mma_f16(o[2 * ntp],     ap, r0, r1);
                mma_f16(o[2 * ntp + 1], ap, r2, r3);
            }
        }
    }

    // Epilogue: normalize, write y as fp16 [B,T,C]
    const float inv0 = 1.f / l0;
    const float inv1 = 1.f / l1;
    const int b = bh >> 4;
    const int h = bh & 15;
    __half* y0 = g_yh + ((size_t)(b * SEQ + row0)) * CDIM + h * 64;
    __half* y1 = g_yh + ((size_t)(b * SEQ + row1)) * CDIM + h * 64;
#pragma unroll
    for (int nt = 0; nt < 8; nt++) {
        int d = nt * 8 + 2 * lk;
        *(uint32_t*)(y0 + d) = h2_u32(o[nt][0] * inv0, o[nt][1] * inv0);
        *(uint32_t*)(y1 + d) = h2_u32(o[nt][2] * inv1, o[nt][3] * inv1);
    }
}

// ---------------------------------------------------------------------------
extern "C" void kernel_launch(void* const* d_in, const int* in_sizes, int n_in,
                              void* d_out, int out_size)
{
    const float* x      = (const float*)d_in[0];
    const float* w_attn = (const float*)d_in[1];
    const float* b_attn = (const float*)d_in[2];
    const float* w_proj = (const float*)d_in[3];
    const float* b_proj = (const float*)d_in[4];
    float* out = (float*)d_out;

    cudaFuncSetAttribute(attn_mma, cudaFuncAttributeMaxDynamicSharedMemorySize,
                         SMEM_ATTN);
    cudaFuncSetAttribute(gemm_mma<true>, cudaFuncAttributeMaxDynamicSharedMemorySize,
                         GEMM_SMEM);
    cudaFuncSetAttribute(gemm_mma<false>, cudaFuncAttributeMaxDynamicSharedMemorySize,
                         GEMM_SMEM);

    void* xh_ptr = nullptr;  cudaGetSymbolAddress(&xh_ptr, g_xh);
    void* yh_ptr = nullptr;  cudaGetSymbolAddress(&yh_ptr, g_yh);
    void* wt1_ptr = nullptr; cudaGetSymbolAddress(&wt1_ptr, g_wt1);
    void* wt2_ptr = nullptr; cudaGetSymbolAddress(&wt2_ptr, g_wt2);

    // 0) merged pre-pass: x fp16 + both weight transposes, one launch
    prepass<<<PRE_BLOCKS, 256>>>(x, w_attn, w_proj,
                                 (__half*)xh_ptr, (__half*)wt1_ptr, (__half*)wt2_ptr);

    // 1) QKV projection (fp16 mma) + scatter to [BH][T][D] (q scaled)
    gemm_mma<true><<<dim3(3072 / 128, MROWS / 128), 128, GEMM_SMEM>>>(
        (const __half*)xh_ptr, (const __half*)wt1_ptr, b_attn, nullptr);

    // 2) Causal flash attention (fp16 mma, exp2 domain)
    attn_mma<<<dim3(SEQ / 128, BH), 256, SMEM_ATTN>>>();

    // 3) Output projection (fp16 mma)
    gemm_mma<false><<<dim3(1024 / 128, MROWS / 128), 128, GEMM_SMEM>>>(
        (const __half*)yh_ptr, (const __half*)wt2_ptr, b_proj, out);
}